// round 13
// baseline (speedup 1.0000x reference)
#include <cuda_runtime.h>
#include <cuda_bf16.h>
#include <cuda_fp16.h>
#include <cstdint>

#define DEVFN static __device__ __forceinline__

constexpr int cB  = 2;
constexpr int cL  = 2048;
constexpr int cDM = 2048;            // D_MODEL
constexpr int cDS = 4096;            // D_SSM
constexpr int cST = 128;             // D_STATE
constexpr int cNH = 64;              // NHEADS
constexpr int cHD = 64;              // HEADDIM
constexpr int cCK = 128;             // CHUNK
constexpr int cNC = cL / cCK;        // 16
constexpr int cDP = 2*cDS + 2*cST + cNH;   // 8512
constexpr int cCD = cDS + 2*cST;           // 4352
constexpr float cEPS = 1e-5f;

constexpr int cNPAD1 = 8704;         // padded N for GEMM1 (34 * 256)

// ---------------- scratch (static device globals; no allocation) ----------
__device__ float g_zx [(size_t)cB*cL*cDP];
__device__ float g_xbc[(size_t)cB*cL*cCD];
__device__ float g_dt [(size_t)cB*cNH*cL];
__device__ float g_ac [(size_t)cB*cNH*cL];
__device__ float g_T  [(size_t)cB*cNH*cNC];
__device__ float g_cs [(size_t)cB*cNC*cNH*cST*cHD];
__device__ float g_pv [(size_t)cB*cNC*cNH*cST*cHD];
__device__ float g_gm [(size_t)cB*cNC*cCK*cCK];
__device__ float g_y  [(size_t)cB*cL*cDS];
__device__ float g_o  [(size_t)cB*cL*cDM];
// fp16 operand buffers
__device__ unsigned short g_ah [(size_t)4096*4096];
__device__ unsigned short g_bh [(size_t)cNPAD1*2048];
__device__ unsigned short g_bl [(size_t)cNPAD1*2048];
__device__ unsigned short g_b2h[(size_t)cDM*cDS];
__device__ unsigned short g_b2l[(size_t)cDM*cDS];

// ---------------- math helpers --------------------------------------------
DEVFN float fexp(float x) {
  float t = x * 1.44269504088896340736f;
  t = fminf(fmaxf(t, -126.0f), 126.0f);
  float fi = rintf(t);
  float f  = t - fi;
  float p = 1.5403530393381610e-4f;
  p = fmaf(p, f, 1.3333558146428443e-3f);
  p = fmaf(p, f, 9.6181291076284772e-3f);
  p = fmaf(p, f, 5.5504108664821580e-2f);
  p = fmaf(p, f, 2.4022650695910071e-1f);
  p = fmaf(p, f, 6.9314718055994531e-1f);
  p = fmaf(p, f, 1.0f);
  int i = (int)fi;
  return __int_as_float((i + 127) << 23) * p;
}
DEVFN float fsig(float x) { return 1.0f / (1.0f + fexp(-x)); }

DEVFN uint32_t smem_to_u32(const void* p) {
  uint32_t a;
  asm("{ .reg .u64 t; cvta.to.shared.u64 t, %1; cvt.u32.u64 %0, t; }"
      : "=r"(a) : "l"(p));
  return a;
}
DEVFN void cp16(uint32_t saddr, const void* gptr) {
  asm volatile("cp.async.cg.shared.global [%0], [%1], 16;"
               :: "r"(saddr), "l"(gptr) : "memory");
}
DEVFN void ldsm4(uint32_t (&r)[4], uint32_t a) {
  asm volatile("ldmatrix.sync.aligned.m8n8.x4.shared.b16 {%0,%1,%2,%3}, [%4];"
    : "=r"(r[0]), "=r"(r[1]), "=r"(r[2]), "=r"(r[3]) : "r"(a));
}
DEVFN void ldsm4t(uint32_t (&r)[4], uint32_t a) {
  asm volatile("ldmatrix.sync.aligned.m8n8.x4.trans.shared.b16 {%0,%1,%2,%3}, [%4];"
    : "=r"(r[0]), "=r"(r[1]), "=r"(r[2]), "=r"(r[3]) : "r"(a));
}
DEVFN void mma16816h(float (&d)[4], const uint32_t (&a)[4], uint32_t b0, uint32_t b1) {
  asm volatile("mma.sync.aligned.m16n8k16.row.col.f32.f16.f16.f32 "
    "{%0,%1,%2,%3},{%4,%5,%6,%7},{%8,%9},{%0,%1,%2,%3};"
    : "+f"(d[0]), "+f"(d[1]), "+f"(d[2]), "+f"(d[3])
    : "r"(a[0]), "r"(a[1]), "r"(a[2]), "r"(a[3]), "r"(b0), "r"(b1));
}
DEVFN void hsplit(float v, __half& h, __half& l) {
  h = __float2half_rn(v);
  l = __float2half_rn(v - __half2float(h));
}

extern __shared__ char dyn_smem[];

// ============= K0a: fp32 -> fp16, no padding ==============================
__global__ void __launch_bounds__(256) k_cvt_h(
    const float* __restrict__ src, unsigned short* __restrict__ dst, long tot)
{
  long i = ((long)blockIdx.x * 256 + threadIdx.x) * 4;
  if (i >= tot) return;
  float4 v = *(const float4*)(src + i);
  __half h0 = __float2half_rn(v.x), h1 = __float2half_rn(v.y);
  __half h2 = __float2half_rn(v.z), h3 = __float2half_rn(v.w);
  ushort4 hv;
  hv.x = *(unsigned short*)&h0; hv.y = *(unsigned short*)&h1;
  hv.z = *(unsigned short*)&h2; hv.w = *(unsigned short*)&h3;
  *(ushort4*)(dst + i) = hv;
}

// ============= K0b: fp32 -> (hi, lo) fp16, with row zero-padding ==========
__global__ void __launch_bounds__(256) k_cvt_hl(
    const float* __restrict__ src, unsigned short* __restrict__ hi,
    unsigned short* __restrict__ lo, int srcRows, int K, long tot)
{
  long i = ((long)blockIdx.x * 256 + threadIdx.x) * 4;
  if (i >= tot) return;
  long row = i / K;
  float4 v = make_float4(0.f, 0.f, 0.f, 0.f);
  if (row < srcRows) v = *(const float4*)(src + i);
  __half h0, h1, h2, h3, l0, l1, l2, l3;
  hsplit(v.x, h0, l0); hsplit(v.y, h1, l1);
  hsplit(v.z, h2, l2); hsplit(v.w, h3, l3);
  ushort4 hv, lv;
  hv.x = *(unsigned short*)&h0; hv.y = *(unsigned short*)&h1;
  hv.z = *(unsigned short*)&h2; hv.w = *(unsigned short*)&h3;
  lv.x = *(unsigned short*)&l0; lv.y = *(unsigned short*)&l1;
  lv.z = *(unsigned short*)&l2; lv.w = *(unsigned short*)&l3;
  *(ushort4*)(hi + i) = hv;
  *(ushort4*)(lo + i) = lv;
}

constexpr int ROWB = 80;   // smem bytes per 32-half row (64B data + 16B pad)

// ============= GEMM-W: 128x256 CTA, 64x64 warp tile, 1 CTA/SM =============
constexpr int W_TA  = 128 * ROWB;              // A tile 10240
constexpr int W_TB  = 256 * ROWB;              // B tile 20480 (each of hi/lo)
constexpr int W_STG = W_TA + 2 * W_TB;         // 51200
constexpr int SMEM_GW = 3 * W_STG;             // 153600

__global__ void __launch_bounds__(256, 1) gemm_mma_w(
    const __half* __restrict__ A,
    const __half* __restrict__ Bh, const __half* __restrict__ Bl,
    float* __restrict__ C, int M, int N, int K)
{
  char* smem = dyn_smem;
  const uint32_t sb0 = smem_to_u32(smem);
  const int tid = threadIdx.x;
  const int lane = tid & 31, wid = tid >> 5;
  const int bm = blockIdx.y * 128, bn = blockIdx.x * 256;
  const int wm = (wid >> 2) * 64, wn = (wid & 3) * 64;

  float acc[4][8][4];
  #pragma unroll
  for (int i = 0; i < 4; ++i)
    #pragma unroll
    for (int j = 0; j < 8; ++j)
      #pragma unroll
      for (int q = 0; q < 4; ++q) acc[i][j][q] = 0.0f;

  auto load_tile = [&](int kt, int stg) {
    const uint32_t sb = sb0 + stg * W_STG;
    const long kb = (long)kt * 32;
    #pragma unroll
    for (int i = 0; i < 2; ++i) {            // A: 128 rows x 4 chunks
      int o = tid + 256 * i;
      int row = o >> 2, seg = o & 3;
      cp16(sb + row * ROWB + seg * 16,
           A + (long)(bm + row) * K + kb + seg * 8);
    }
    #pragma unroll
    for (int i = 0; i < 4; ++i) {            // B: 256 rows x 4 chunks, hi+lo
      int o = tid + 256 * i;
      int row = o >> 2, seg = o & 3;
      uint32_t soff = row * ROWB + seg * 16;
      long gb = (long)(bn + row) * K + kb + seg * 8;
      cp16(sb + W_TA + soff,        Bh + gb);
      cp16(sb + W_TA + W_TB + soff, Bl + gb);
    }
    asm volatile("cp.async.commit_group;" ::: "memory");
  };

  const int KT = K >> 5;
  load_tile(0, 0);
  load_tile(1, 1);
  for (int kt = 0; kt < KT; ++kt) {
    const int stg = kt % 3;
    if (kt < KT - 1) {
      asm volatile("cp.async.wait_group 1;" ::: "memory");
    } else {
      asm volatile("cp.async.wait_group 0;" ::: "memory");
    }
    __syncthreads();
    if (kt + 2 < KT) load_tile(kt + 2, (kt + 2) % 3);
    const uint32_t sb = sb0 + stg * W_STG;
    #pragma unroll
    for (int h = 0; h < 2; ++h) {
      uint32_t af[4][4];
      #pragma unroll
      for (int mi = 0; mi < 4; ++mi) {
        uint32_t ad = sb + (uint32_t)(wm + mi*16 + (lane & 15)) * ROWB
                         + h*32 + (lane >> 4) * 16;
        ldsm4(af[mi], ad);
      }
      #pragma unroll
      for (int nj2 = 0; nj2 < 4; ++nj2) {
        uint32_t bd = sb + W_TA
          + (uint32_t)(wn + nj2*16 + (lane & 7) + ((lane >> 4) << 3)) * ROWB
          + h*32 + ((lane >> 3) & 1) * 16;
        uint32_t bhf[4], blf[4];
        ldsm4(bhf, bd);
        ldsm4(blf, bd + W_TB);
        #pragma unroll
        for (int mi = 0; mi < 4; ++mi)
          #pragma unroll
          for (int s = 0; s < 2; ++s)
            mma16816h(acc[mi][nj2*2+s], af[mi], bhf[2*s], bhf[2*s+1]);
        #pragma unroll
        for (int mi = 0; mi < 4; ++mi)
          #pragma unroll
          for (int s = 0; s < 2; ++s)
            mma16816h(acc[mi][nj2*2+s], af[mi], blf[2*s], blf[2*s+1]);
      }
    }
  }

  #pragma unroll
  for (int mi = 0; mi < 4; ++mi) {
    int row = bm + wm + mi*16 + (lane >> 2);
    #pragma unroll
    for (int nj = 0; nj < 8; ++nj) {
      int col = bn + wn + nj*8 + (lane & 3)*2;
      if (col < N) {
        *(float2*)(C + (long)row * N + col) =
            make_float2(acc[mi][nj][0], acc[mi][nj][1]);
        *(float2*)(C + (long)(row + 8) * N + col) =
            make_float2(acc[mi][nj][2], acc[mi][nj][3]);
      }
    }
  }
}

// ============= GEMM-S: 128x128 CTA (R11 config) for GEMM2 =================
constexpr int TILEB = 128 * ROWB;         // 10240
constexpr int STGB  = 3 * TILEB;
constexpr int SMEM_GS = 3 * STGB;         // 92160

__global__ void __launch_bounds__(256, 2) gemm_mma_s(
    const __half* __restrict__ A,
    const __half* __restrict__ Bh, const __half* __restrict__ Bl,
    float* __restrict__ C, int M, int N, int K)
{
  char* smem = dyn_smem;
  const uint32_t sb0 = smem_to_u32(smem);
  const int tid = threadIdx.x;
  const int lane = tid & 31, wid = tid >> 5;
  const int bm = blockIdx.y * 128, bn = blockIdx.x * 128;
  const int wm = (wid >> 1) * 32, wn = (wid & 1) * 64;

  float acc[2][8][4];
  #pragma unroll
  for (int i = 0; i < 2; ++i)
    #pragma unroll
    for (int j = 0; j < 8; ++j)
      #pragma unroll
      for (int q = 0; q < 4; ++q) acc[i][j][q] = 0.0f;

  auto load_tile = [&](int kt, int stg) {
    const uint32_t sb = sb0 + stg * STGB;
    const long kb = (long)kt * 32;
    #pragma unroll
    for (int i = 0; i < 2; ++i) {
      int o = tid + 256 * i;
      int row = o >> 2, seg = o & 3;
      uint32_t soff = row * ROWB + seg * 16;
      long ga = (long)(bm + row) * K + kb + seg * 8;
      long gb = (long)(bn + row) * K + kb + seg * 8;
      cp16(sb + soff,             A  + ga);
      cp16(sb + TILEB + soff,     Bh + gb);
      cp16(sb + 2*TILEB + soff,   Bl + gb);
    }
    asm volatile("cp.async.commit_group;" ::: "memory");
  };

  const int KT = K >> 5;
  load_tile(0, 0);
  load_tile(1, 1);
  for (int kt = 0; kt < KT; ++kt) {
    const int stg = kt % 3;
    if (kt < KT - 1) {
      asm volatile("cp.async.wait_group 1;" ::: "memory");
    } else {
      asm volatile("cp.async.wait_group 0;" ::: "memory");
    }
    __syncthreads();
    if (kt + 2 < KT) load_tile(kt + 2, (kt + 2) % 3);
    const uint32_t sb = sb0 + stg * STGB;
    #pragma unroll
    for (int h = 0; h < 2; ++h) {
      uint32_t ah[2][4];
      #pragma unroll
      for (int mi = 0; mi < 2; ++mi) {
        uint32_t ad = sb + (uint32_t)(wm + mi*16 + (lane & 15)) * ROWB
                         + h*32 + (lane >> 4) * 16;
        ldsm4(ah[mi], ad);
      }
      #pragma unroll
      for (int nj2 = 0; nj2 < 4; ++nj2) {
        uint32_t bd = sb + TILEB
          + (uint32_t)(wn + nj2*16 + (lane & 7) + ((lane >> 4) << 3)) * ROWB
          + h*32 + ((lane >> 3) & 1) * 16;
        uint32_t bh4[4], bl4[4];
        ldsm4(bh4, bd);
        ldsm4(bl4, bd + TILEB);
        #pragma unroll
        for (int mi = 0; mi < 2; ++mi) {
          #pragma unroll
          for (int s = 0; s < 2; ++s) {
            int nj = nj2 * 2 + s;
            mma16816h(acc[mi][nj], ah[mi], bh4[2*s], bh4[2*s+1]);
            mma16816h(acc[mi][nj], ah[mi], bl4[2*s], bl4[2*s+1]);
          }
        }
      }
    }
  }

  #pragma unroll
  for (int mi = 0; mi < 2; ++mi) {
    int row = bm + wm + mi*16 + (lane >> 2);
    #pragma unroll
    for (int nj = 0; nj < 8; ++nj) {
      int col = bn + wn + nj*8 + (lane & 3)*2;
      if (col < N) {
        *(float2*)(C + (long)row * N + col) =
            make_float2(acc[mi][nj][0], acc[mi][nj][1]);
        *(float2*)(C + (long)(row + 8) * N + col) =
            make_float2(acc[mi][nj][2], acc[mi][nj][3]);
      }
    }
  }
}

// ============= K2: conv1d + SiLU + softplus(dt), 8 rows per block =========
constexpr int CTL = 8;
__global__ void __launch_bounds__(256) k_conv(
    const float* __restrict__ conv_w, const float* __restrict__ conv_b,
    const float* __restrict__ dt_bias)
{
  const int blk = blockIdx.x;
  const int b = blk / (cL / CTL), lt = blk % (cL / CTL);
  const int l0 = lt * CTL;
  const int tid = threadIdx.x;
  const size_t rb = ((size_t)(b * cL + l0)) * cDP + cDS;
  const size_t ob = ((size_t)(b * cL + l0)) * cCD;
  #pragma unroll 1
  for (int q = 0; q < 5; ++q) {
    int c4 = tid + q * 256;
    if (c4 >= cCD / 4) break;
    int c = c4 * 4;
    float4 wa = *(const float4*)(conv_w + c*3);
    float4 wb = *(const float4*)(conv_w + c*3 + 4);
    float4 wc = *(const float4*)(conv_w + c*3 + 8);
    float4 bs = *(const float4*)(conv_b + c);
    float4 xr[CTL + 2];
    #pragma unroll
    for (int r = 0; r < CTL + 2; ++r) {
      int gl = l0 - 2 + r;
      xr[r] = (gl >= 0) ? *(const float4*)(&g_zx[rb + (size_t)(r - 2) * cDP + c])
                        : make_float4(0.f, 0.f, 0.f, 0.f);
    }
    #pragma unroll
    for (int t = 0; t < CTL; ++t) {
      float4 x2 = xr[t], x1 = xr[t + 1], x0 = xr[t + 2];
      float4 s;
      s.x = bs.x + x2.x*wa.x + x1.x*wa.y + x0.x*wa.z;
      s.y = bs.y + x2.y*wa.w + x1.y*wb.x + x0.y*wb.y;
      s.z = bs.z + x2.z*wb.z + x1.z*wb.w + x0.z*wc.x;
      s.w = bs.w + x2.w*wc.y + x1.w*wc.z + x0.w*wc.w;
      s.x *= fsig(s.x); s.y *= fsig(s.y); s.z *= fsig(s.z); s.w *= fsig(s.w);
      *(float4*)(&g_xbc[ob + (size_t)t * cCD + c]) = s;
    }
  }
  #pragma unroll
  for (int i = 0; i < 2; ++i) {
    int idx = tid + i * 256;
    int hh = idx & 63, t = idx >> 6;
    float v = g_zx[((size_t)(b * cL + l0 + t)) * cDP + (cDP - cNH) + hh]
              + dt_bias[hh];
    float sp = (v > 15.0f) ? v : log1pf(expf(v));
    g_dt[((size_t)b * cNH + hh) * cL + l0 + t] = sp;
  }
}

// ============= K3: per-chunk inclusive cumsum of dt*A =====================
__global__ void __launch_bounds__(128) k_scan(const float* __restrict__ A_log)
{
  const int h = blockIdx.x, c = blockIdx.y, b = blockIdx.z;
  const int l = threadIdx.x;
  const float ah = -expf(A_log[h]);
  const size_t base = ((size_t)b * cNH + h) * cL + c * cCK;
  __shared__ float s[128];
  s[l] = g_dt[base + l] * ah;
  __syncthreads();
  #pragma unroll
  for (int off = 1; off < 128; off <<= 1) {
    float t = (l >= off) ? s[l - off] : 0.0f;
    __syncthreads();
    s[l] += t;
    __syncthreads();
  }
  g_ac[base + l] = s[l];
  if (l == 127) g_T[((size_t)b * cNH + h) * cNC + c] = s[127];
}

// ============= K4: chunk states (fp16 mma) ================================
constexpr int S_AS  = 136;
constexpr int S_BS  = 72;
constexpr int S_Ao  = 0;
constexpr int S_BHo = 128 * S_AS * 2;
constexpr int S_BLo = S_BHo + 128 * S_BS * 2;
constexpr int S_SCo = S_BLo + 128 * S_BS * 2;
constexpr int S_SMEM = S_SCo + 512;

__global__ void __launch_bounds__(256, 2) k_states()
{
  char* sm = dyn_smem;
  __half* Ap = (__half*)(sm + S_Ao);
  __half* Bhp = (__half*)(sm + S_BHo);
  __half* Blp = (__half*)(sm + S_BLo);
  float* sc = (float*)(sm + S_SCo);
  const uint32_t sb = smem_to_u32(sm);
  const int h = blockIdx.x, c = blockIdx.y, b = blockIdx.z;
  const int tid = threadIdx.x, lane = tid & 31, wid = tid >> 5;
  const size_t rowbase = ((size_t)(b * cL + c * cCK)) * cCD;
  const size_t acb = ((size_t)b * cNH + h) * cL + c * cCK;
  if (tid < 128) {
    float T = g_T[((size_t)b * cNH + h) * cNC + c];
    sc[tid] = g_dt[acb + tid] * fexp(T - g_ac[acb + tid]);
  }
  __syncthreads();
  #pragma unroll 1
  for (int q = 0; q < 16; ++q) {
    int i = (tid + q * 256) * 4;
    int l = i >> 7, n = i & 127;
    float4 v = *(const float4*)&g_xbc[rowbase + (size_t)l * cCD + cDS + n];
    float vv[4] = {v.x, v.y, v.z, v.w};
    #pragma unroll
    for (int j = 0; j < 4; ++j)
      Ap[l * S_AS + n + j] = __float2half_rn(vv[j]);
  }
  #pragma unroll 1
  for (int q = 0; q < 8; ++q) {
    int i = (tid + q * 256) * 4;
    int l = i >> 6, p = i & 63;
    float4 x = *(const float4*)&g_xbc[rowbase + (size_t)l * cCD + h * cHD + p];
    float s = sc[l];
    float xv[4] = {x.x * s, x.y * s, x.z * s, x.w * s};
    #pragma unroll
    for (int j = 0; j < 4; ++j) {
      __half hh, ll;
      hsplit(xv[j], hh, ll);
      Bhp[l * S_BS + p + j] = hh; Blp[l * S_BS + p + j] = ll;
    }
  }
  __syncthreads();

  const int wm = (wid >> 1) * 32, wn = (wid & 1) * 32;
  float acc[2][4][4];
  #pragma unroll
  for (int mi = 0; mi < 2; ++mi)
    #pragma unroll
    for (int nj = 0; nj < 4; ++nj)
      #pragma unroll
      for (int q = 0; q < 4; ++q) acc[mi][nj][q] = 0.0f;

  #pragma unroll
  for (int kk = 0; kk < 8; ++kk) {
    uint32_t ah4[2][4];
    #pragma unroll
    for (int mi = 0; mi < 2; ++mi) {
      uint32_t ad = sb + S_Ao
        + (uint32_t)(kk*16 + (lane & 7) + ((lane >> 4) << 3)) * (S_AS * 2)
        + (uint32_t)(wm + mi*16 + (lane & 8)) * 2;
      ldsm4t(ah4[mi], ad);
    }
    uint32_t bh4[2][4], bl4[2][4];
    #pragma unroll
    for (int nj2 = 0; nj2 < 2; ++nj2) {
      uint32_t bd = sb + S_BHo
        + (uint32_t)(kk*16 + (lane & 15)) * (S_BS * 2)
        + (uint32_t)(wn + nj2*16 + ((lane >> 4) << 3)) * 2;
      ldsm4t(bh4[nj2], bd);
      ldsm4t(bl4[nj2], bd + (S_BLo - S_BHo));
    }
    #pragma unroll
    for (int nj2 = 0; nj2 < 2; ++nj2)
      #pragma unroll
      for (int mi = 0; mi < 2; ++mi)
        #pragma unroll
        for (int s2 = 0; s2 < 2; ++s2)
          mma16816h(acc[mi][nj2*2+s2], ah4[mi], bh4[nj2][2*s2], bh4[nj2][2*s2+1]);
    #pragma unroll
    for (int nj2 = 0; nj2 < 2; ++nj2)
      #pragma unroll
      for (int mi = 0; mi < 2; ++mi)
        #pragma unroll
        for (int s2 = 0; s2 < 2; ++s2)
          mma16816h(acc[mi][nj2*2+s2], ah4[mi], bl4[nj2][2*s2], bl4[nj2][2*s2+1]);
  }

  const size_t ob = (((size_t)b * cNC + c) * cNH + h) * (cST * cHD);
  #pragma unroll
  for (int mi = 0; mi < 2; ++mi) {
    int row = wm + mi*16 + (lane >> 2);
    #pragma unroll
    for (int nj = 0; nj < 4; ++nj) {
      int col = wn + nj*8 + (lane & 3)*2;
      *(float2*)&g_cs[ob + (size_t)row * cHD + col] =
          make_float2(acc[mi][nj][0], acc[mi][nj][1]);
      *(float2*)&g_cs[ob + (size_t)(row + 8) * cHD + col] =
          make_float2(acc[mi][nj][2], acc[mi][nj][3]);
    }
  }
}

// ============= K5: inter-chunk carry scan =================================
__global__ void __launch_bounds__(256) k_carry()
{
  const int bh = blockIdx.x;
  const int b = bh >> 6, h = bh & 63;
  const int tid = threadIdx.x;
  float carry[32];
  #pragma unroll
  for (int j = 0; j < 32; ++j) carry[j] = 0.0f;
  for (int c = 0; c < cNC; ++c) {
    if (c > 0) {
      float eT = fexp(g_T[(size_t)bh * cNC + (c - 1)]);
      const size_t inb = (((size_t)b * cNC + (c - 1)) * cNH + h) * (cST * cHD);
      #pragma unroll
      for (int j = 0; j < 32; ++j)
        carry[j] = carry[j] * eT + g_cs[inb + tid + j * 256];
    }
    const size_t ob = (((size_t)b * cNC + c) * cNH + h) * (cST * cHD);
    #pragma unroll
    for (int j = 0; j < 32; ++j)
      g_pv[ob + tid + j * 256] = carry[j];
  }
}

// ============= K5.5: unmasked G = C * B^T per (b,c) =======================
__global__ void __launch_bounds__(256) k_gmat()
{
  float* smf = (float*)dyn_smem;
  float* Ct = smf;
  float* Bt = smf + 128 * 132;
  const int c = blockIdx.x, b = blockIdx.y;
  const int tid = threadIdx.x;
  const size_t rowbase = ((size_t)(b * cL + c * cCK)) * cCD;
  #pragma unroll 1
  for (int q = 0; q < 16; ++q) {
    int i = tid + q * 256;
    int l = i >> 5, nq = i & 31;
    const float* src = &g_xbc[rowbase + (size_t)l * cCD];
    float4 cv = *(const float4*)(src + cDS + cST + nq * 4);
    float4 bv = *(const float4*)(src + cDS + nq * 4);
    int n = nq * 4;
    Ct[(n+0)*132 + l] = cv.x; Ct[(n+1)*132 + l] = cv.y;
    Ct[(n+2)*132 + l] = cv.z; Ct[(n+3)*132 + l] = cv.w;
    Bt[(n+0)*132 + l] = bv.x; Bt[(n+1)*132 + l] = bv.y;
    Bt[(n+2)*132 + l] = bv.z; Bt[(n+3)*132 + l] = bv.w;
  }
  __syncthreads();
  const int ty = tid >> 4, tx = tid & 15;
  const int l0 = ty * 8, s0 = tx * 8;
  float accG[8][8] = {};
  for (int n = 0; n < cST; ++n) {
    float4 a0 = *(const float4*)&Ct[n*132 + l0];
    float4 a1 = *(const float4*)&Ct[n*132 + l0 + 4];
    float4 b0 = *(const float4*)&Bt[n*132 + s0];
    float4 b1 = *(const float4*)&Bt[n*132 + s0 + 4];
    float a[8]  = {a0.x, a0.y, a0.z, a0.w, a1.x, a1.y, a1.z, a1.w};
    float bb[8] = {b0.x, b0.y, b0.z, b0.w, b1.x, b1.y, b1.z, b1.w};
    #pragma unroll
    for (int i = 0; i < 8; ++i)
      #pragma unroll
      for (int j = 0; j < 8; ++j) accG[i][j] += a[i] * bb[j];
  }
  const size_t gb = ((size_t)(b * cNC + c)) * (cCK * cCK);
  #pragma unroll
  for (int i = 0; i < 8; ++i) {
    #pragma unroll
    for (int j = 0; j < 4; ++j) {
      *(float2*)&g_gm[gb + (size_t)(l0 + i) * cCK + s0 + 2*j] =
          make_float2(accG[i][2*j], accG[i][2*j+1]);
    }
  }
}

// ============= K6: SSD Y kernel (fp16 mma, 2 passes) ======================
constexpr int Y_AS = 136;
constexpr int Y_BS = 72;
constexpr int Y_Ao  = 0;
constexpr int Y_BHo = 128 * Y_AS * 2;
constexpr int Y_BLo = Y_BHo + 128 * Y_BS * 2;
constexpr int Y_ACS = Y_BLo + 128 * Y_BS * 2;
constexpr int Y_DTS = Y_ACS + 512;
constexpr int Y_SMEM = Y_DTS + 512;

__global__ void __launch_bounds__(256, 2) k_ssd_y(const float* __restrict__ Dv)
{
  char* sm = dyn_smem;
  __half* Ap  = (__half*)(sm + Y_Ao);
  __half* Bhp = (__half*)(sm + Y_BHo);
  __half* Blp = (__half*)(sm + Y_BLo);
  float* acs = (float*)(sm + Y_ACS);
  float* dts = (float*)(sm + Y_DTS);
  const uint32_t sb = smem_to_u32(sm);
  const int h = blockIdx.x, c = blockIdx.y, b = blockIdx.z;
  const int tid = threadIdx.x, lane = tid & 31, wid = tid >> 5;
  const size_t rowbase = ((size_t)(b * cL + c * cCK)) * cCD;
  const size_t acb = ((size_t)b * cNH + h) * cL + c * cCK;
  if (tid < 128) { acs[tid] = g_ac[acb + tid]; dts[tid] = g_dt[acb + tid]; }
  __syncthreads();

  const size_t gb = ((size_t)(b * cNC + c)) * (cCK * cCK);
  #pragma unroll 1
  for (int q = 0; q < 16; ++q) {
    int i = (tid + q * 256) * 4;
    int l = i >> 7, s = i & 127;
    float4 g = *(const float4*)&g_gm[gb + i];
    float al = acs[l];
    float gv[4] = {g.x, g.y, g.z, g.w};
    #pragma unroll
    for (int j = 0; j < 4; ++j) {
      int ss = s + j;
      float m = (ss <= l) ? fexp(al - acs[ss]) : 0.0f;
      Ap[l * Y_AS + ss] = __float2half_rn(gv[j] * m);
    }
  }
  #pragma unroll 1
  for (int q = 0; q < 8; ++q) {
    int i = (tid + q * 256) * 4;
    int s = i >> 6, p = i & 63;
    float4 x = *(const float4*)&g_xbc[rowbase + (size_t)s * cCD + h * cHD + p];
    float dv = dts[s];
    float xv[4] = {x.x * dv, x.y * dv, x.z * dv, x.w * dv};
    #pragma unroll
    for (int j = 0; j < 4; ++j) {
      __half hh, ll;
      hsplit(xv[j], hh, ll);
      Bhp[s * Y_BS + p + j] = hh; Blp[s * Y_BS + p + j] = ll;
    }
  }
  __syncthreads();

  const int wm = (wid >> 1) * 32, wn = (wid & 1) * 32;
  float acc[2][4][4];
  #pragma unroll
  for (int mi = 0; mi < 2; ++mi)
    #pragma unroll
    for (int nj = 0; nj < 4; ++nj)
      #pragma unroll
      for (int q = 0; q < 4; ++q) acc[mi][nj][q] = 0.0f;

  auto mma_pass = [&]() {
    #pragma unroll
    for (int kk = 0; kk < 8; ++kk) {
      uint32_t ah4[2][4];
      #pragma unroll
      for (int mi = 0; mi < 2; ++mi) {
        uint32_t ad = sb + Y_Ao
          + (uint32_t)(wm + mi*16 + (lane & 15)) * (Y_AS * 2)
          + kk*32 + (lane >> 4) * 16;
        ldsm4(ah4[mi], ad);
      }
      uint32_t bh4[2][4], bl4[2][4];
      #pragma unroll
      for (int nj2 = 0; nj2 < 2; ++nj2) {
        uint32_t bd = sb + Y_BHo
          + (uint32_t)(kk*16 + (lane & 15)) * (Y_BS * 2)
          + (uint32_t)(wn + nj2*16 + ((lane >> 4) << 3)) * 2;
        ldsm4t(bh4[nj2], bd);
        ldsm4t(bl4[nj2], bd + (Y_BLo - Y_BHo));
      }
      #pragma unroll
      for (int nj2 = 0; nj2 < 2; ++nj2)
        #pragma unroll
        for (int mi = 0; mi < 2; ++mi)
          #pragma unroll
          for (int s2 = 0; s2 < 2; ++s2)
            mma16816h(acc[mi][nj2*2+s2], ah4[mi], bh4[nj2][2*s2], bh4[nj2][2*s2+1]);
      #pragma unroll
      for (int nj2 = 0; nj2 < 2; ++nj2)
        #pragma unroll
        for (int mi = 0; mi < 2; ++mi)
          #pragma unroll
          for (int s2 = 0; s2 < 2; ++s2)
            mma16816h(acc[mi][nj2*2+s2], ah4[mi], bl4[nj2][2*s2], bl4[nj2][2*s2+1]);
    }
  };
  mma_pass();
  __syncthreads();

  #pragma unroll 1
  for (int q = 0; q < 16; ++q) {
    int i = (tid + q * 256) * 4;
    int l = i >> 7, n = i & 127;
    float4 cv = *(const float4*)&g_xbc[rowbase + (size_t)l * cCD + cDS + cST + n];
    float e = fexp(acs[l]);
    float cvv[4] = {cv.x * e, cv.y * e, cv.z * e, cv.w * e};
    #pragma unroll
    for (int j = 0; j < 4; ++j)
      Ap[l * Y_AS + n + j] = __float2half_rn(cvv[j]);
  }
  {
    const size_t pb = (((size_t)b * cNC + c) * cNH + h) * (cST * cHD);
    #pragma unroll 1
    for (int q = 0; q < 8; ++q) {
      int i = (tid + q * 256) * 4;
      int n = i >> 6, p = i & 63;
      float4 pv = *(const float4*)&g_pv[pb + i];
      float pvv[4] = {pv.x, pv.y, pv.z, pv.w};
      #pragma unroll
      for (int j = 0; j < 4; ++j) {
        __half hh, ll;
        hsplit(pvv[j], hh, ll);
        Bhp[n * Y_BS + p + j] = hh; Blp[n * Y_BS + p + j] = ll;
      }
    }
  }
  __syncthreads();
  mma_pass();

  const float Dh = Dv[h];
  #pragma unroll
  for (int mi = 0; mi < 2; ++mi) {
    int row = wm + mi*16 + (lane >> 2);
    #pragma unroll
    for (int nj = 0; nj < 4; ++nj) {
      int col = wn + nj*8 + (lane & 3)*2;
      float2 x0 = *(const float2*)&g_xbc[rowbase + (size_t)row * cCD + h * cHD + col];
      float2 x1 = *(const float2*)&g_xbc[rowbase + (size_t)(row+8) * cCD + h * cHD + col];
      size_t y0 = ((size_t)(b * cL + c * cCK + row)) * cDS + h * cHD + col;
      size_t y1 = ((size_t)(b * cL + c * cCK + row + 8)) * cDS + h * cHD + col;
      *(float2*)&g_y[y0] = make_float2(acc[mi][nj][0] + Dh * x0.x,
                                       acc[mi][nj][1] + Dh * x0.y);
      *(float2*)&g_y[y1] = make_float2(acc[mi][nj][2] + Dh * x1.x,
                                       acc[mi][nj][3] + Dh * x1.y);
    }
  }
}

// ============= K7: gate (silu(z)) + RMSNorm + fp16 cvt (fused) ============
__global__ void __launch_bounds__(256) k_gate_norm(const float* __restrict__ norm_w)
{
  const int row = blockIdx.x;
  const int tid = threadIdx.x;
  const size_t zb = (size_t)row * cDP;
  const size_t yb = (size_t)row * cDS;
  float v[16];
  float ss = 0.0f;
  #pragma unroll
  for (int q = 0; q < 16; ++q) {
    int i = tid + q * 256;
    float z = g_zx[zb + i];
    float y = g_y[yb + i];
    float t = y * z * fsig(z);
    v[q] = t;
    ss += t * t;
  }
  #pragma unroll
  for (int o = 16; o > 0; o >>= 1) ss += __shfl_xor_sync(0xffffffffu, ss, o);
  __shared__ float red[8];
  if ((tid & 31) == 0) red[tid >> 5] = ss;
  __syncthreads();
  float tot = 0.0f;
  #pragma unroll
  for (int j = 0; j < 8; ++j) tot += red[j];
  const float scale = rsqrtf(tot / (float)cDS + cEPS);
  #pragma unroll
  for (int q = 0; q < 16; ++q) {
    int i = tid + q * 256;
    float t = v[q] * scale * norm_w[i];
    __half hh = __float2half_rn(t);
    g_ah[yb + i] = *(unsigned short*)&hh;
  }
}

// ============= K9: out + reverse(out) =====================================
__global__ void __launch_bounds__(256) k_revadd(float* __restrict__ out)
{
  const int idx4 = blockIdx.x * 256 + threadIdx.x;
  const int tot4 = cB * cL * cDM / 4;
  if (idx4 >= tot4) return;
  const int i = idx4 * 4;
  const int b = i / (cL * cDM);
  const int r = i - b * (cL * cDM);
  const int l = r / cDM;
  const int d = r - l * cDM;
  const size_t rev = ((size_t)b * cL + (cL - 1 - l)) * cDM + d;
  float4 a = *(const float4*)(&g_o[i]);
  float4 c = *(const float4*)(&g_o[rev]);
  a.x += c.x; a.y += c.y; a.z += c.z; a.w += c.w;
  *(float4*)(out + i) = a;
}

// ==========================================================================
extern "C" void kernel_launch(void* const* d_in, const int* in_sizes, int n_in,
                              void* d_out, int out_size) {
  const float* u       = (const float*)d_in[0];
  const float* W_in    = (const float*)d_in[1];
  const float* conv_w  = (const float*)d_in[2];
  const float* conv_b  = (const float*)d_in[3];
  const float* dt_bias = (const float*)d_in[4];
  const float* A_log   = (const float*)d_in[5];
  const float* Dv      = (const float*)d_in[6];
  const float* norm_w  = (const float*)d_in[7];
  const float* W_out   = (const float*)d_in[8];
  float* out = (float*)d_out;

  float* zx; cudaGetSymbolAddress((void**)&zx, g_zx);
  float* ob; cudaGetSymbolAddress((void**)&ob, g_o);
  unsigned short *ah, *bh, *bl, *b2h, *b2l;
  cudaGetSymbolAddress((void**)&ah,  g_ah);
  cudaGetSymbolAddress((void**)&bh,  g_bh);
  cudaGetSymbolAddress((void**)&bl,  g_bl);
  cudaGetSymbolAddress((void**)&b2h, g_b2h);
  cudaGetSymbolAddress((void**)&b2l, g_b2l);

  cudaFuncSetAttribute(gemm_mma_w, cudaFuncAttributeMaxDynamicSharedMemorySize,
                       SMEM_GW);
  cudaFuncSetAttribute(gemm_mma_s, cudaFuncAttributeMaxDynamicSharedMemorySize,
                       SMEM_GS);
  cudaFuncSetAttribute(k_gmat, cudaFuncAttributeMaxDynamicSharedMemorySize,
                       2 * 128 * 132 * 4);
  cudaFuncSetAttribute(k_states, cudaFuncAttributeMaxDynamicSharedMemorySize,
                       S_SMEM);
  cudaFuncSetAttribute(k_ssd_y, cudaFuncAttributeMaxDynamicSharedMemorySize,
                       Y_SMEM);

  const int M = cB * cL;   // 4096

  // --- prep: u -> fp16; W_in, W_out -> fp16 hi/lo (launch #4 = GEMM1) ---
  {
    long totA = (long)M * cDM;
    k_cvt_h<<<(unsigned)((totA/4 + 255)/256), 256>>>(u, ah, totA);
    long totB = (long)cNPAD1 * cDM;
    k_cvt_hl<<<(unsigned)((totB/4 + 255)/256), 256>>>(W_in, bh, bl, cDP, cDM, totB);
    long totB2 = (long)cDM * cDS;
    k_cvt_hl<<<(unsigned)((totB2/4 + 255)/256), 256>>>(W_out, b2h, b2l, cDM, cDS, totB2);
  }
  // --- GEMM1 (wide): zx[4096, 8512] ---
  {
    dim3 grid(cNPAD1 / 256, M / 128);
    gemm_mma_w<<<grid, 256, SMEM_GW>>>(
        (const __half*)ah, (const __half*)bh, (const __half*)bl,
        zx, M, cDP, cDM);
  }
  // --- conv + silu + dt ---
  k_conv<<<cB * cL / CTL, 256>>>(conv_w, conv_b, dt_bias);
  // --- per-chunk cumsum ---
  { dim3 grid(cNH, cNC, cB); k_scan<<<grid, 128>>>(A_log); }
  // --- chunk states (fp16 mma) ---
  { dim3 grid(cNH, cNC, cB); k_states<<<grid, 256, S_SMEM>>>(); }
  // --- carry scan ---
  k_carry<<<cB * cNH, 256>>>();
  // --- unmasked G ---
  { dim3 grid(cNC, cB); k_gmat<<<grid, 256, 2 * 128 * 132 * 4>>>(); }
  // --- Y (fp16 mma) ---
  { dim3 grid(cNH, cNC, cB); k_ssd_y<<<grid, 256, Y_SMEM>>>(Dv); }
  // --- gate + rmsnorm + fp16 cvt (fused) ---
  k_gate_norm<<<cB * cL, 256>>>(norm_w);
  // --- GEMM2 (std): o[4096, 2048] ---
  {
    dim3 grid(cDM / 128, M / 128);
    gemm_mma_s<<<grid, 256, SMEM_GS>>>(
        (const __half*)ah, (const __half*)b2h, (const __half*)b2l,
        ob, M, cDM, cDS);
  }
  // --- out + reverse(out) ---
  k_revadd<<<(cB * cL * cDM / 4 + 255) / 256, 256>>>(out);
}

// round 14
// speedup vs baseline: 1.0897x; 1.0897x over previous
#include <cuda_runtime.h>
#include <cuda_bf16.h>
#include <cuda_fp16.h>
#include <cstdint>

#define DEVFN static __device__ __forceinline__

constexpr int cB  = 2;
constexpr int cL  = 2048;
constexpr int cDM = 2048;
constexpr int cDS = 4096;
constexpr int cST = 128;
constexpr int cNH = 64;
constexpr int cHD = 64;
constexpr int cCK = 128;
constexpr int cNC = cL / cCK;        // 16
constexpr int cDP = 2*cDS + 2*cST + cNH;   // 8512
constexpr int cCD = cDS + 2*cST;           // 4352
constexpr float cEPS = 1e-5f;

constexpr int cNPAD1 = 8704;

// ---------------- scratch ----------
__device__ float g_zx [(size_t)cB*cL*cDP];
__device__ float g_xbc[(size_t)cB*cL*cCD];
__device__ float g_dt [(size_t)cB*cNH*cL];
__device__ float g_ac [(size_t)cB*cNH*cL];
__device__ float g_T  [(size_t)cB*cNH*cNC];
__device__ float g_cs [(size_t)cB*cNC*cNH*cST*cHD];
__device__ float g_pv [(size_t)cB*cNC*cNH*cST*cHD];
__device__ float g_gm [(size_t)cB*cNC*cCK*cCK];
__device__ float g_y  [(size_t)cB*cL*cDS];
__device__ float g_o  [(size_t)cB*cL*cDM];
__device__ unsigned short g_ah [(size_t)4096*4096];
__device__ unsigned short g_bh [(size_t)cNPAD1*2048];
__device__ unsigned short g_bl [(size_t)cNPAD1*2048];
__device__ unsigned short g_b2h[(size_t)cDM*cDS];
__device__ unsigned short g_b2l[(size_t)cDM*cDS];

// ---------------- math helpers --------------------------------------------
DEVFN float fexp(float x) {
  float t = x * 1.44269504088896340736f;
  t = fminf(fmaxf(t, -126.0f), 126.0f);
  float fi = rintf(t);
  float f  = t - fi;
  float p = 1.5403530393381610e-4f;
  p = fmaf(p, f, 1.3333558146428443e-3f);
  p = fmaf(p, f, 9.6181291076284772e-3f);
  p = fmaf(p, f, 5.5504108664821580e-2f);
  p = fmaf(p, f, 2.4022650695910071e-1f);
  p = fmaf(p, f, 6.9314718055994531e-1f);
  p = fmaf(p, f, 1.0f);
  int i = (int)fi;
  return __int_as_float((i + 127) << 23) * p;
}
DEVFN float fsig(float x) { return 1.0f / (1.0f + fexp(-x)); }

DEVFN uint32_t smem_to_u32(const void* p) {
  uint32_t a;
  asm("{ .reg .u64 t; cvta.to.shared.u64 t, %1; cvt.u32.u64 %0, t; }"
      : "=r"(a) : "l"(p));
  return a;
}
DEVFN void cp16(uint32_t saddr, const void* gptr) {
  asm volatile("cp.async.cg.shared.global [%0], [%1], 16;"
               :: "r"(saddr), "l"(gptr) : "memory");
}
DEVFN void ldsm4(uint32_t (&r)[4], uint32_t a) {
  asm volatile("ldmatrix.sync.aligned.m8n8.x4.shared.b16 {%0,%1,%2,%3}, [%4];"
    : "=r"(r[0]), "=r"(r[1]), "=r"(r[2]), "=r"(r[3]) : "r"(a));
}
DEVFN void ldsm4t(uint32_t (&r)[4], uint32_t a) {
  asm volatile("ldmatrix.sync.aligned.m8n8.x4.trans.shared.b16 {%0,%1,%2,%3}, [%4];"
    : "=r"(r[0]), "=r"(r[1]), "=r"(r[2]), "=r"(r[3]) : "r"(a));
}
DEVFN void mma16816h(float (&d)[4], const uint32_t (&a)[4], uint32_t b0, uint32_t b1) {
  asm volatile("mma.sync.aligned.m16n8k16.row.col.f32.f16.f16.f32 "
    "{%0,%1,%2,%3},{%4,%5,%6,%7},{%8,%9},{%0,%1,%2,%3};"
    : "+f"(d[0]), "+f"(d[1]), "+f"(d[2]), "+f"(d[3])
    : "r"(a[0]), "r"(a[1]), "r"(a[2]), "r"(a[3]), "r"(b0), "r"(b1));
}
DEVFN void hsplit(float v, __half& h, __half& l) {
  h = __float2half_rn(v);
  l = __float2half_rn(v - __half2float(h));
}

extern __shared__ char dyn_smem[];

// ============= K0a: fp32 -> fp16 ==========================================
__global__ void __launch_bounds__(256) k_cvt_h(
    const float* __restrict__ src, unsigned short* __restrict__ dst, long tot)
{
  long i = ((long)blockIdx.x * 256 + threadIdx.x) * 4;
  if (i >= tot) return;
  float4 v = *(const float4*)(src + i);
  __half h0 = __float2half_rn(v.x), h1 = __float2half_rn(v.y);
  __half h2 = __float2half_rn(v.z), h3 = __float2half_rn(v.w);
  ushort4 hv;
  hv.x = *(unsigned short*)&h0; hv.y = *(unsigned short*)&h1;
  hv.z = *(unsigned short*)&h2; hv.w = *(unsigned short*)&h3;
  *(ushort4*)(dst + i) = hv;
}

// ============= K0b: fp32 -> (hi, lo) fp16, row zero-padding ===============
__global__ void __launch_bounds__(256) k_cvt_hl(
    const float* __restrict__ src, unsigned short* __restrict__ hi,
    unsigned short* __restrict__ lo, int srcRows, int K, long tot)
{
  long i = ((long)blockIdx.x * 256 + threadIdx.x) * 4;
  if (i >= tot) return;
  long row = i / K;
  float4 v = make_float4(0.f, 0.f, 0.f, 0.f);
  if (row < srcRows) v = *(const float4*)(src + i);
  __half h0, h1, h2, h3, l0, l1, l2, l3;
  hsplit(v.x, h0, l0); hsplit(v.y, h1, l1);
  hsplit(v.z, h2, l2); hsplit(v.w, h3, l3);
  ushort4 hv, lv;
  hv.x = *(unsigned short*)&h0; hv.y = *(unsigned short*)&h1;
  hv.z = *(unsigned short*)&h2; hv.w = *(unsigned short*)&h3;
  lv.x = *(unsigned short*)&l0; lv.y = *(unsigned short*)&l1;
  lv.z = *(unsigned short*)&l2; lv.w = *(unsigned short*)&l3;
  *(ushort4*)(hi + i) = hv;
  *(ushort4*)(lo + i) = lv;
}

// ============= fp16 2-MMA GEMM (R11-proven 128x128 config) ================
constexpr int ROWB  = 80;
constexpr int TILEB = 128 * ROWB;
constexpr int STGB  = 3 * TILEB;
constexpr int SMEM_GEMM = 3 * STGB;       // 92160

__global__ void __launch_bounds__(256, 2) gemm_mma(
    const __half* __restrict__ A,
    const __half* __restrict__ Bh, const __half* __restrict__ Bl,
    float* __restrict__ C, int M, int N, int K)
{
  char* smem = dyn_smem;
  const uint32_t sb0 = smem_to_u32(smem);
  const int tid = threadIdx.x;
  const int lane = tid & 31, wid = tid >> 5;
  const int bm = blockIdx.y * 128, bn = blockIdx.x * 128;
  const int wm = (wid >> 1) * 32, wn = (wid & 1) * 64;

  float acc[2][8][4];
  #pragma unroll
  for (int i = 0; i < 2; ++i)
    #pragma unroll
    for (int j = 0; j < 8; ++j)
      #pragma unroll
      for (int q = 0; q < 4; ++q) acc[i][j][q] = 0.0f;

  auto load_tile = [&](int kt, int stg) {
    const uint32_t sb = sb0 + stg * STGB;
    const long kb = (long)kt * 32;
    #pragma unroll
    for (int i = 0; i < 2; ++i) {
      int o = tid + 256 * i;
      int row = o >> 2, seg = o & 3;
      uint32_t soff = row * ROWB + seg * 16;
      long ga = (long)(bm + row) * K + kb + seg * 8;
      long gb = (long)(bn + row) * K + kb + seg * 8;
      cp16(sb + soff,             A  + ga);
      cp16(sb + TILEB + soff,     Bh + gb);
      cp16(sb + 2*TILEB + soff,   Bl + gb);
    }
    asm volatile("cp.async.commit_group;" ::: "memory");
  };

  const int KT = K >> 5;
  load_tile(0, 0);
  load_tile(1, 1);
  for (int kt = 0; kt < KT; ++kt) {
    const int stg = kt % 3;
    if (kt < KT - 1) {
      asm volatile("cp.async.wait_group 1;" ::: "memory");
    } else {
      asm volatile("cp.async.wait_group 0;" ::: "memory");
    }
    __syncthreads();
    if (kt + 2 < KT) load_tile(kt + 2, (kt + 2) % 3);
    const uint32_t sb = sb0 + stg * STGB;
    #pragma unroll
    for (int h = 0; h < 2; ++h) {
      uint32_t ah[2][4];
      #pragma unroll
      for (int mi = 0; mi < 2; ++mi) {
        uint32_t ad = sb + (uint32_t)(wm + mi*16 + (lane & 15)) * ROWB
                         + h*32 + (lane >> 4) * 16;
        ldsm4(ah[mi], ad);
      }
      #pragma unroll
      for (int nj2 = 0; nj2 < 4; ++nj2) {
        uint32_t bd = sb + TILEB
          + (uint32_t)(wn + nj2*16 + (lane & 7) + ((lane >> 4) << 3)) * ROWB
          + h*32 + ((lane >> 3) & 1) * 16;
        uint32_t bh4[4], bl4[4];
        ldsm4(bh4, bd);
        ldsm4(bl4, bd + TILEB);
        #pragma unroll
        for (int mi = 0; mi < 2; ++mi) {
          #pragma unroll
          for (int s = 0; s < 2; ++s) {
            int nj = nj2 * 2 + s;
            mma16816h(acc[mi][nj], ah[mi], bh4[2*s], bh4[2*s+1]);
            mma16816h(acc[mi][nj], ah[mi], bl4[2*s], bl4[2*s+1]);
          }
        }
      }
    }
  }

  #pragma unroll
  for (int mi = 0; mi < 2; ++mi) {
    int row = bm + wm + mi*16 + (lane >> 2);
    #pragma unroll
    for (int nj = 0; nj < 8; ++nj) {
      int col = bn + wn + nj*8 + (lane & 3)*2;
      if (col < N) {
        *(float2*)(C + (long)row * N + col) =
            make_float2(acc[mi][nj][0], acc[mi][nj][1]);
        *(float2*)(C + (long)(row + 8) * N + col) =
            make_float2(acc[mi][nj][2], acc[mi][nj][3]);
      }
    }
  }
}

// ============= K2: conv1d + SiLU + softplus(dt), 8 rows per block =========
constexpr int CTL = 8;
__global__ void __launch_bounds__(256) k_conv(
    const float* __restrict__ conv_w, const float* __restrict__ conv_b,
    const float* __restrict__ dt_bias)
{
  const int blk = blockIdx.x;
  const int b = blk / (cL / CTL), lt = blk % (cL / CTL);
  const int l0 = lt * CTL;
  const int tid = threadIdx.x;
  const size_t rb = ((size_t)(b * cL + l0)) * cDP + cDS;
  const size_t ob = ((size_t)(b * cL + l0)) * cCD;
  #pragma unroll 1
  for (int q = 0; q < 5; ++q) {
    int c4 = tid + q * 256;
    if (c4 >= cCD / 4) break;
    int c = c4 * 4;
    float4 wa = *(const float4*)(conv_w + c*3);
    float4 wb = *(const float4*)(conv_w + c*3 + 4);
    float4 wc = *(const float4*)(conv_w + c*3 + 8);
    float4 bs = *(const float4*)(conv_b + c);
    float4 xr[CTL + 2];
    #pragma unroll
    for (int r = 0; r < CTL + 2; ++r) {
      int gl = l0 - 2 + r;
      xr[r] = (gl >= 0) ? *(const float4*)(&g_zx[rb + (size_t)(r - 2) * cDP + c])
                        : make_float4(0.f, 0.f, 0.f, 0.f);
    }
    #pragma unroll
    for (int t = 0; t < CTL; ++t) {
      float4 x2 = xr[t], x1 = xr[t + 1], x0 = xr[t + 2];
      float4 s;
      s.x = bs.x + x2.x*wa.x + x1.x*wa.y + x0.x*wa.z;
      s.y = bs.y + x2.y*wa.w + x1.y*wb.x + x0.y*wb.y;
      s.z = bs.z + x2.z*wb.z + x1.z*wb.w + x0.z*wc.x;
      s.w = bs.w + x2.w*wc.y + x1.w*wc.z + x0.w*wc.w;
      s.x *= fsig(s.x); s.y *= fsig(s.y); s.z *= fsig(s.z); s.w *= fsig(s.w);
      *(float4*)(&g_xbc[ob + (size_t)t * cCD + c]) = s;
    }
  }
  #pragma unroll
  for (int i = 0; i < 2; ++i) {
    int idx = tid + i * 256;
    int hh = idx & 63, t = idx >> 6;
    float v = g_zx[((size_t)(b * cL + l0 + t)) * cDP + (cDP - cNH) + hh]
              + dt_bias[hh];
    float sp = (v > 15.0f) ? v : log1pf(expf(v));
    g_dt[((size_t)b * cNH + hh) * cL + l0 + t] = sp;
  }
}

// ============= K3: per-chunk inclusive cumsum of dt*A =====================
__global__ void __launch_bounds__(128) k_scan(const float* __restrict__ A_log)
{
  const int h = blockIdx.x, c = blockIdx.y, b = blockIdx.z;
  const int l = threadIdx.x;
  const float ah = -expf(A_log[h]);
  const size_t base = ((size_t)b * cNH + h) * cL + c * cCK;
  __shared__ float s[128];
  s[l] = g_dt[base + l] * ah;
  __syncthreads();
  #pragma unroll
  for (int off = 1; off < 128; off <<= 1) {
    float t = (l >= off) ? s[l - off] : 0.0f;
    __syncthreads();
    s[l] += t;
    __syncthreads();
  }
  g_ac[base + l] = s[l];
  if (l == 127) g_T[((size_t)b * cNH + h) * cNC + c] = s[127];
}

// ============= K4: chunk states (fp16 mma, single-B) ======================
constexpr int S_AS  = 136;
constexpr int S_BS  = 72;
constexpr int S_Ao  = 0;
constexpr int S_Bo  = 128 * S_AS * 2;          // 34816
constexpr int S_SCo = S_Bo + 128 * S_BS * 2;   // 53248
constexpr int S_SMEM = S_SCo + 512;            // 53760

__global__ void __launch_bounds__(256, 2) k_states()
{
  char* sm = dyn_smem;
  __half* Ap = (__half*)(sm + S_Ao);
  __half* Bp = (__half*)(sm + S_Bo);
  float* sc = (float*)(sm + S_SCo);
  const uint32_t sb = smem_to_u32(sm);
  const int h = blockIdx.x, c = blockIdx.y, b = blockIdx.z;
  const int tid = threadIdx.x, lane = tid & 31, wid = tid >> 5;
  const size_t rowbase = ((size_t)(b * cL + c * cCK)) * cCD;
  const size_t acb = ((size_t)b * cNH + h) * cL + c * cCK;
  if (tid < 128) {
    float T = g_T[((size_t)b * cNH + h) * cNC + c];
    sc[tid] = g_dt[acb + tid] * fexp(T - g_ac[acb + tid]);
  }
  __syncthreads();
  #pragma unroll 1
  for (int q = 0; q < 16; ++q) {
    int i = (tid + q * 256) * 4;
    int l = i >> 7, n = i & 127;
    float4 v = *(const float4*)&g_xbc[rowbase + (size_t)l * cCD + cDS + n];
    float vv[4] = {v.x, v.y, v.z, v.w};
    #pragma unroll
    for (int j = 0; j < 4; ++j)
      Ap[l * S_AS + n + j] = __float2half_rn(vv[j]);
  }
  #pragma unroll 1
  for (int q = 0; q < 8; ++q) {
    int i = (tid + q * 256) * 4;
    int l = i >> 6, p = i & 63;
    float4 x = *(const float4*)&g_xbc[rowbase + (size_t)l * cCD + h * cHD + p];
    float s = sc[l];
    float xv[4] = {x.x * s, x.y * s, x.z * s, x.w * s};
    #pragma unroll
    for (int j = 0; j < 4; ++j)
      Bp[l * S_BS + p + j] = __float2half_rn(xv[j]);
  }
  __syncthreads();

  const int wm = (wid >> 1) * 32, wn = (wid & 1) * 32;
  float acc[2][4][4];
  #pragma unroll
  for (int mi = 0; mi < 2; ++mi)
    #pragma unroll
    for (int nj = 0; nj < 4; ++nj)
      #pragma unroll
      for (int q = 0; q < 4; ++q) acc[mi][nj][q] = 0.0f;

  #pragma unroll
  for (int kk = 0; kk < 8; ++kk) {
    uint32_t ah4[2][4];
    #pragma unroll
    for (int mi = 0; mi < 2; ++mi) {
      uint32_t ad = sb + S_Ao
        + (uint32_t)(kk*16 + (lane & 7) + ((lane >> 4) << 3)) * (S_AS * 2)
        + (uint32_t)(wm + mi*16 + (lane & 8)) * 2;
      ldsm4t(ah4[mi], ad);
    }
    uint32_t bf[2][4];
    #pragma unroll
    for (int nj2 = 0; nj2 < 2; ++nj2) {
      uint32_t bd = sb + S_Bo
        + (uint32_t)(kk*16 + (lane & 15)) * (S_BS * 2)
        + (uint32_t)(wn + nj2*16 + ((lane >> 4) << 3)) * 2;
      ldsm4t(bf[nj2], bd);
    }
    #pragma unroll
    for (int nj2 = 0; nj2 < 2; ++nj2)
      #pragma unroll
      for (int mi = 0; mi < 2; ++mi)
        #pragma unroll
        for (int s2 = 0; s2 < 2; ++s2)
          mma16816h(acc[mi][nj2*2+s2], ah4[mi], bf[nj2][2*s2], bf[nj2][2*s2+1]);
  }

  const size_t ob = (((size_t)b * cNC + c) * cNH + h) * (cST * cHD);
  #pragma unroll
  for (int mi = 0; mi < 2; ++mi) {
    int row = wm + mi*16 + (lane >> 2);
    #pragma unroll
    for (int nj = 0; nj < 4; ++nj) {
      int col = wn + nj*8 + (lane & 3)*2;
      *(float2*)&g_cs[ob + (size_t)row * cHD + col] =
          make_float2(acc[mi][nj][0], acc[mi][nj][1]);
      *(float2*)&g_cs[ob + (size_t)(row + 8) * cHD + col] =
          make_float2(acc[mi][nj][2], acc[mi][nj][3]);
    }
  }
}

// ============= K5: inter-chunk carry scan (4-way state split) =============
__global__ void __launch_bounds__(256) k_carry()
{
  const int blk = blockIdx.x;            // cB*cNH*4
  const int bh = blk >> 2, qt = blk & 3;
  const int b = bh >> 6, h = bh & 63;
  const int off = qt * 2048;
  const int tid = threadIdx.x;
  float carry[8];
  #pragma unroll
  for (int j = 0; j < 8; ++j) carry[j] = 0.0f;
  for (int c = 0; c < cNC; ++c) {
    if (c > 0) {
      float eT = fexp(g_T[(size_t)bh * cNC + (c - 1)]);
      const size_t inb = (((size_t)b * cNC + (c - 1)) * cNH + h) * (cST * cHD) + off;
      #pragma unroll
      for (int j = 0; j < 8; ++j)
        carry[j] = carry[j] * eT + g_cs[inb + tid + j * 256];
    }
    const size_t ob = (((size_t)b * cNC + c) * cNH + h) * (cST * cHD) + off;
    #pragma unroll
    for (int j = 0; j < 8; ++j)
      g_pv[ob + tid + j * 256] = carry[j];
  }
}

// ============= K5.5: unmasked G = C * B^T per (b,c) =======================
__global__ void __launch_bounds__(256) k_gmat()
{
  float* smf = (float*)dyn_smem;
  float* Ct = smf;
  float* Bt = smf + 128 * 132;
  const int c = blockIdx.x, b = blockIdx.y;
  const int tid = threadIdx.x;
  const size_t rowbase = ((size_t)(b * cL + c * cCK)) * cCD;
  #pragma unroll 1
  for (int q = 0; q < 16; ++q) {
    int i = tid + q * 256;
    int l = i >> 5, nq = i & 31;
    const float* src = &g_xbc[rowbase + (size_t)l * cCD];
    float4 cv = *(const float4*)(src + cDS + cST + nq * 4);
    float4 bv = *(const float4*)(src + cDS + nq * 4);
    int n = nq * 4;
    Ct[(n+0)*132 + l] = cv.x; Ct[(n+1)*132 + l] = cv.y;
    Ct[(n+2)*132 + l] = cv.z; Ct[(n+3)*132 + l] = cv.w;
    Bt[(n+0)*132 + l] = bv.x; Bt[(n+1)*132 + l] = bv.y;
    Bt[(n+2)*132 + l] = bv.z; Bt[(n+3)*132 + l] = bv.w;
  }
  __syncthreads();
  const int ty = tid >> 4, tx = tid & 15;
  const int l0 = ty * 8, s0 = tx * 8;
  float accG[8][8] = {};
  for (int n = 0; n < cST; ++n) {
    float4 a0 = *(const float4*)&Ct[n*132 + l0];
    float4 a1 = *(const float4*)&Ct[n*132 + l0 + 4];
    float4 b0 = *(const float4*)&Bt[n*132 + s0];
    float4 b1 = *(const float4*)&Bt[n*132 + s0 + 4];
    float a[8]  = {a0.x, a0.y, a0.z, a0.w, a1.x, a1.y, a1.z, a1.w};
    float bb[8] = {b0.x, b0.y, b0.z, b0.w, b1.x, b1.y, b1.z, b1.w};
    #pragma unroll
    for (int i = 0; i < 8; ++i)
      #pragma unroll
      for (int j = 0; j < 8; ++j) accG[i][j] += a[i] * bb[j];
  }
  const size_t gb = ((size_t)(b * cNC + c)) * (cCK * cCK);
  #pragma unroll
  for (int i = 0; i < 8; ++i) {
    #pragma unroll
    for (int j = 0; j < 4; ++j) {
      *(float2*)&g_gm[gb + (size_t)(l0 + i) * cCK + s0 + 2*j] =
          make_float2(accG[i][2*j], accG[i][2*j+1]);
    }
  }
}

// ============= K6: SSD Y kernel (fp16 mma single-B, 2 passes) =============
constexpr int Y_AS = 136;
constexpr int Y_BS = 72;
constexpr int Y_Ao  = 0;
constexpr int Y_Bo  = 128 * Y_AS * 2;          // 34816
constexpr int Y_ACS = Y_Bo + 128 * Y_BS * 2;   // 53248
constexpr int Y_DTS = Y_ACS + 512;             // 53760
constexpr int Y_SMEM = Y_DTS + 512;            // 54272

__global__ void __launch_bounds__(256, 2) k_ssd_y(const float* __restrict__ Dv)
{
  char* sm = dyn_smem;
  __half* Ap = (__half*)(sm + Y_Ao);
  __half* Bp = (__half*)(sm + Y_Bo);
  float* acs = (float*)(sm + Y_ACS);
  float* dts = (float*)(sm + Y_DTS);
  const uint32_t sb = smem_to_u32(sm);
  const int h = blockIdx.x, c = blockIdx.y, b = blockIdx.z;
  const int tid = threadIdx.x, lane = tid & 31, wid = tid >> 5;
  const size_t rowbase = ((size_t)(b * cL + c * cCK)) * cCD;
  const size_t acb = ((size_t)b * cNH + h) * cL + c * cCK;
  if (tid < 128) { acs[tid] = g_ac[acb + tid]; dts[tid] = g_dt[acb + tid]; }
  __syncthreads();

  const size_t gb = ((size_t)(b * cNC + c)) * (cCK * cCK);
  #pragma unroll 1
  for (int q = 0; q < 16; ++q) {
    int i = (tid + q * 256) * 4;
    int l = i >> 7, s = i & 127;
    float4 g = *(const float4*)&g_gm[gb + i];
    float al = acs[l];
    float gv[4] = {g.x, g.y, g.z, g.w};
    #pragma unroll
    for (int j = 0; j < 4; ++j) {
      int ss = s + j;
      float m = (ss <= l) ? fexp(al - acs[ss]) : 0.0f;
      Ap[l * Y_AS + ss] = __float2half_rn(gv[j] * m);
    }
  }
  #pragma unroll 1
  for (int q = 0; q < 8; ++q) {
    int i = (tid + q * 256) * 4;
    int s = i >> 6, p = i & 63;
    float4 x = *(const float4*)&g_xbc[rowbase + (size_t)s * cCD + h * cHD + p];
    float dv = dts[s];
    float xv[4] = {x.x * dv, x.y * dv, x.z * dv, x.w * dv};
    #pragma unroll
    for (int j = 0; j < 4; ++j)
      Bp[s * Y_BS + p + j] = __float2half_rn(xv[j]);
  }
  __syncthreads();

  const int wm = (wid >> 1) * 32, wn = (wid & 1) * 32;
  float acc[2][4][4];
  #pragma unroll
  for (int mi = 0; mi < 2; ++mi)
    #pragma unroll
    for (int nj = 0; nj < 4; ++nj)
      #pragma unroll
      for (int q = 0; q < 4; ++q) acc[mi][nj][q] = 0.0f;

  auto mma_pass = [&]() {
    #pragma unroll
    for (int kk = 0; kk < 8; ++kk) {
      uint32_t ah4[2][4];
      #pragma unroll
      for (int mi = 0; mi < 2; ++mi) {
        uint32_t ad = sb + Y_Ao
          + (uint32_t)(wm + mi*16 + (lane & 15)) * (Y_AS * 2)
          + kk*32 + (lane >> 4) * 16;
        ldsm4(ah4[mi], ad);
      }
      uint32_t bf[2][4];
      #pragma unroll
      for (int nj2 = 0; nj2 < 2; ++nj2) {
        uint32_t bd = sb + Y_Bo
          + (uint32_t)(kk*16 + (lane & 15)) * (Y_BS * 2)
          + (uint32_t)(wn + nj2*16 + ((lane >> 4) << 3)) * 2;
        ldsm4t(bf[nj2], bd);
      }
      #pragma unroll
      for (int nj2 = 0; nj2 < 2; ++nj2)
        #pragma unroll
        for (int mi = 0; mi < 2; ++mi)
          #pragma unroll
          for (int s2 = 0; s2 < 2; ++s2)
            mma16816h(acc[mi][nj2*2+s2], ah4[mi], bf[nj2][2*s2], bf[nj2][2*s2+1]);
    }
  };
  mma_pass();          // Y += Gm @ X'
  __syncthreads();

  #pragma unroll 1
  for (int q = 0; q < 16; ++q) {
    int i = (tid + q * 256) * 4;
    int l = i >> 7, n = i & 127;
    float4 cv = *(const float4*)&g_xbc[rowbase + (size_t)l * cCD + cDS + cST + n];
    float e = fexp(acs[l]);
    float cvv[4] = {cv.x * e, cv.y * e, cv.z * e, cv.w * e};
    #pragma unroll
    for (int j = 0; j < 4; ++j)
      Ap[l * Y_AS + n + j] = __float2half_rn(cvv[j]);
  }
  {
    const size_t pb = (((size_t)b * cNC + c) * cNH + h) * (cST * cHD);
    #pragma unroll 1
    for (int q = 0; q < 8; ++q) {
      int i = (tid + q * 256) * 4;
      int n = i >> 6, p = i & 63;
      float4 pv = *(const float4*)&g_pv[pb + i];
      float pvv[4] = {pv.x, pv.y, pv.z, pv.w};
      #pragma unroll
      for (int j = 0; j < 4; ++j)
        Bp[n * Y_BS + p + j] = __float2half_rn(pvv[j]);
    }
  }
  __syncthreads();
  mma_pass();          // Y += Ce @ P

  const float Dh = Dv[h];
  #pragma unroll
  for (int mi = 0; mi < 2; ++mi) {
    int row = wm + mi*16 + (lane >> 2);
    #pragma unroll
    for (int nj = 0; nj < 4; ++nj) {
      int col = wn + nj*8 + (lane & 3)*2;
      float2 x0 = *(const float2*)&g_xbc[rowbase + (size_t)row * cCD + h * cHD + col];
      float2 x1 = *(const float2*)&g_xbc[rowbase + (size_t)(row+8) * cCD + h * cHD + col];
      size_t y0 = ((size_t)(b * cL + c * cCK + row)) * cDS + h * cHD + col;
      size_t y1 = ((size_t)(b * cL + c * cCK + row + 8)) * cDS + h * cHD + col;
      *(float2*)&g_y[y0] = make_float2(acc[mi][nj][0] + Dh * x0.x,
                                       acc[mi][nj][1] + Dh * x0.y);
      *(float2*)&g_y[y1] = make_float2(acc[mi][nj][2] + Dh * x1.x,
                                       acc[mi][nj][3] + Dh * x1.y);
    }
  }
}

// ============= K7: gate (silu(z)) + RMSNorm + fp16 cvt (fused) ============
__global__ void __launch_bounds__(256) k_gate_norm(const float* __restrict__ norm_w)
{
  const int row = blockIdx.x;
  const int tid = threadIdx.x;
  const size_t zb = (size_t)row * cDP;
  const size_t yb = (size_t)row * cDS;
  float v[16];
  float ss = 0.0f;
  #pragma unroll
  for (int q = 0; q < 16; ++q) {
    int i = tid + q * 256;
    float z = g_zx[zb + i];
    float y = g_y[yb + i];
    float t = y * z * fsig(z);
    v[q] = t;
    ss += t * t;
  }
  #pragma unroll
  for (int o = 16; o > 0; o >>= 1) ss += __shfl_xor_sync(0xffffffffu, ss, o);
  __shared__ float red[8];
  if ((tid & 31) == 0) red[tid >> 5] = ss;
  __syncthreads();
  float tot = 0.0f;
  #pragma unroll
  for (int j = 0; j < 8; ++j) tot += red[j];
  const float scale = rsqrtf(tot / (float)cDS + cEPS);
  #pragma unroll
  for (int q = 0; q < 16; ++q) {
    int i = tid + q * 256;
    float t = v[q] * scale * norm_w[i];
    __half hh = __float2half_rn(t);
    g_ah[yb + i] = *(unsigned short*)&hh;
  }
}

// ============= K9: out + reverse(out) =====================================
__global__ void __launch_bounds__(256) k_revadd(float* __restrict__ out)
{
  const int idx4 = blockIdx.x * 256 + threadIdx.x;
  const int tot4 = cB * cL * cDM / 4;
  if (idx4 >= tot4) return;
  const int i = idx4 * 4;
  const int b = i / (cL * cDM);
  const int r = i - b * (cL * cDM);
  const int l = r / cDM;
  const int d = r - l * cDM;
  const size_t rev = ((size_t)b * cL + (cL - 1 - l)) * cDM + d;
  float4 a = *(const float4*)(&g_o[i]);
  float4 c = *(const float4*)(&g_o[rev]);
  a.x += c.x; a.y += c.y; a.z += c.z; a.w += c.w;
  *(float4*)(out + i) = a;
}

// ==========================================================================
extern "C" void kernel_launch(void* const* d_in, const int* in_sizes, int n_in,
                              void* d_out, int out_size) {
  const float* u       = (const float*)d_in[0];
  const float* W_in    = (const float*)d_in[1];
  const float* conv_w  = (const float*)d_in[2];
  const float* conv_b  = (const float*)d_in[3];
  const float* dt_bias = (const float*)d_in[4];
  const float* A_log   = (const float*)d_in[5];
  const float* Dv      = (const float*)d_in[6];
  const float* norm_w  = (const float*)d_in[7];
  const float* W_out   = (const float*)d_in[8];
  float* out = (float*)d_out;

  float* zx; cudaGetSymbolAddress((void**)&zx, g_zx);
  float* ob; cudaGetSymbolAddress((void**)&ob, g_o);
  unsigned short *ah, *bh, *bl, *b2h, *b2l;
  cudaGetSymbolAddress((void**)&ah,  g_ah);
  cudaGetSymbolAddress((void**)&bh,  g_bh);
  cudaGetSymbolAddress((void**)&bl,  g_bl);
  cudaGetSymbolAddress((void**)&b2h, g_b2h);
  cudaGetSymbolAddress((void**)&b2l, g_b2l);

  cudaFuncSetAttribute(gemm_mma, cudaFuncAttributeMaxDynamicSharedMemorySize,
                       SMEM_GEMM);
  cudaFuncSetAttribute(k_gmat, cudaFuncAttributeMaxDynamicSharedMemorySize,
                       2 * 128 * 132 * 4);
  cudaFuncSetAttribute(k_states, cudaFuncAttributeMaxDynamicSharedMemorySize,
                       S_SMEM);
  cudaFuncSetAttribute(k_ssd_y, cudaFuncAttributeMaxDynamicSharedMemorySize,
                       Y_SMEM);

  const int M = cB * cL;   // 4096

  // --- prep: u -> fp16; W_in, W_out -> fp16 hi/lo ---
  {
    long totA = (long)M * cDM;
    k_cvt_h<<<(unsigned)((totA/4 + 255)/256), 256>>>(u, ah, totA);
    long totB = (long)cNPAD1 * cDM;
    k_cvt_hl<<<(unsigned)((totB/4 + 255)/256), 256>>>(W_in, bh, bl, cDP, cDM, totB);
    long totB2 = (long)cDM * cDS;
    k_cvt_hl<<<(unsigned)((totB2/4 + 255)/256), 256>>>(W_out, b2h, b2l, cDM, cDS, totB2);
  }
  // --- GEMM1: zx[4096, 8512] ---
  {
    dim3 grid(cNPAD1 / 128, M / 128);
    gemm_mma<<<grid, 256, SMEM_GEMM>>>(
        (const __half*)ah, (const __half*)bh, (const __half*)bl,
        zx, M, cDP, cDM);
  }
  // --- conv + silu + dt ---
  k_conv<<<cB * cL / CTL, 256>>>(conv_w, conv_b, dt_bias);
  // --- per-chunk cumsum ---
  { dim3 grid(cNH, cNC, cB); k_scan<<<grid, 128>>>(A_log); }
  // --- chunk states (fp16 mma) ---
  { dim3 grid(cNH, cNC, cB); k_states<<<grid, 256, S_SMEM>>>(); }
  // --- carry scan (4-way split) ---
  k_carry<<<cB * cNH * 4, 256>>>();
  // --- unmasked G ---
  { dim3 grid(cNC, cB); k_gmat<<<grid, 256, 2 * 128 * 132 * 4>>>(); }
  // --- Y (fp16 mma) ---
  { dim3 grid(cNH, cNC, cB); k_ssd_y<<<grid, 256, Y_SMEM>>>(Dv); }
  // --- gate + rmsnorm + fp16 cvt (fused) ---
  k_gate_norm<<<cB * cL, 256>>>(norm_w);
  // --- GEMM2: o[4096, 2048] ---
  {
    dim3 grid(cDM / 128, M / 128);
    gemm_mma<<<grid, 256, SMEM_GEMM>>>(
        (const __half*)ah, (const __half*)b2h, (const __half*)b2l,
        ob, M, cDM, cDS);
  }
  // --- out + reverse(out) ---
  k_revadd<<<(cB * cL * cDM / 4 + 255) / 256, 256>>>(out);
}

// round 15
// speedup vs baseline: 1.6042x; 1.4722x over previous
#include <cuda_runtime.h>
#include <cuda_bf16.h>
#include <cuda_fp16.h>
#include <cstdint>

#define DEVFN static __device__ __forceinline__

constexpr int cB  = 2;
constexpr int cL  = 2048;
constexpr int cDM = 2048;
constexpr int cDS = 4096;
constexpr int cST = 128;
constexpr int cNH = 64;
constexpr int cHD = 64;
constexpr int cCK = 128;
constexpr int cNC = cL / cCK;        // 16
constexpr int cDP = 2*cDS + 2*cST + cNH;   // 8512
constexpr int cCD = cDS + 2*cST;           // 4352
constexpr float cEPS = 1e-5f;

constexpr int cNPAD1 = 8704;

// ---------------- scratch ----------
__device__ float g_zx [(size_t)cB*cL*cDP];
__device__ float g_xbc[(size_t)cB*cL*cCD];
__device__ float g_dt [(size_t)cB*cNH*cL];
__device__ float g_ac [(size_t)cB*cNH*cL];
__device__ float g_T  [(size_t)cB*cNH*cNC];
__device__ float g_cs [(size_t)cB*cNC*cNH*cST*cHD];
__device__ float g_pv [(size_t)cB*cNC*cNH*cST*cHD];
__device__ float g_gm [(size_t)cB*cNC*cCK*cCK];
__device__ float g_y  [(size_t)cB*cL*cDS];
__device__ float g_o  [(size_t)cB*cL*cDM];
__device__ unsigned short g_ah [(size_t)4096*4096];
__device__ unsigned short g_bh [(size_t)cNPAD1*2048];
__device__ unsigned short g_b2h[(size_t)cDM*cDS];

// ---------------- math helpers --------------------------------------------
DEVFN float fexp(float x) {
  float t = x * 1.44269504088896340736f;
  t = fminf(fmaxf(t, -126.0f), 126.0f);
  float fi = rintf(t);
  float f  = t - fi;
  float p = 1.5403530393381610e-4f;
  p = fmaf(p, f, 1.3333558146428443e-3f);
  p = fmaf(p, f, 9.6181291076284772e-3f);
  p = fmaf(p, f, 5.5504108664821580e-2f);
  p = fmaf(p, f, 2.4022650695910071e-1f);
  p = fmaf(p, f, 6.9314718055994531e-1f);
  p = fmaf(p, f, 1.0f);
  int i = (int)fi;
  return __int_as_float((i + 127) << 23) * p;
}
DEVFN float fsig(float x) { return 1.0f / (1.0f + fexp(-x)); }

DEVFN uint32_t smem_to_u32(const void* p) {
  uint32_t a;
  asm("{ .reg .u64 t; cvta.to.shared.u64 t, %1; cvt.u32.u64 %0, t; }"
      : "=r"(a) : "l"(p));
  return a;
}
DEVFN void cp16(uint32_t saddr, const void* gptr) {
  asm volatile("cp.async.cg.shared.global [%0], [%1], 16;"
               :: "r"(saddr), "l"(gptr) : "memory");
}
DEVFN void ldsm4(uint32_t (&r)[4], uint32_t a) {
  asm volatile("ldmatrix.sync.aligned.m8n8.x4.shared.b16 {%0,%1,%2,%3}, [%4];"
    : "=r"(r[0]), "=r"(r[1]), "=r"(r[2]), "=r"(r[3]) : "r"(a));
}
DEVFN void ldsm4t(uint32_t (&r)[4], uint32_t a) {
  asm volatile("ldmatrix.sync.aligned.m8n8.x4.trans.shared.b16 {%0,%1,%2,%3}, [%4];"
    : "=r"(r[0]), "=r"(r[1]), "=r"(r[2]), "=r"(r[3]) : "r"(a));
}
DEVFN void mma16816h(float (&d)[4], const uint32_t (&a)[4], uint32_t b0, uint32_t b1) {
  asm volatile("mma.sync.aligned.m16n8k16.row.col.f32.f16.f16.f32 "
    "{%0,%1,%2,%3},{%4,%5,%6,%7},{%8,%9},{%0,%1,%2,%3};"
    : "+f"(d[0]), "+f"(d[1]), "+f"(d[2]), "+f"(d[3])
    : "r"(a[0]), "r"(a[1]), "r"(a[2]), "r"(a[3]), "r"(b0), "r"(b1));
}

extern __shared__ char dyn_smem[];

// ============= K0a: fp32 -> fp16 ==========================================
__global__ void __launch_bounds__(256) k_cvt_h(
    const float* __restrict__ src, unsigned short* __restrict__ dst, long tot)
{
  long i = ((long)blockIdx.x * 256 + threadIdx.x) * 4;
  if (i >= tot) return;
  float4 v = *(const float4*)(src + i);
  __half h0 = __float2half_rn(v.x), h1 = __float2half_rn(v.y);
  __half h2 = __float2half_rn(v.z), h3 = __float2half_rn(v.w);
  ushort4 hv;
  hv.x = *(unsigned short*)&h0; hv.y = *(unsigned short*)&h1;
  hv.z = *(unsigned short*)&h2; hv.w = *(unsigned short*)&h3;
  *(ushort4*)(dst + i) = hv;
}

// ============= K0b: fp32 -> fp16 with row zero-padding ====================
__global__ void __launch_bounds__(256) k_cvt_h_pad(
    const float* __restrict__ src, unsigned short* __restrict__ dst,
    int srcRows, int K, long tot)
{
  long i = ((long)blockIdx.x * 256 + threadIdx.x) * 4;
  if (i >= tot) return;
  long row = i / K;
  float4 v = make_float4(0.f, 0.f, 0.f, 0.f);
  if (row < srcRows) v = *(const float4*)(src + i);
  __half h0 = __float2half_rn(v.x), h1 = __float2half_rn(v.y);
  __half h2 = __float2half_rn(v.z), h3 = __float2half_rn(v.w);
  ushort4 hv;
  hv.x = *(unsigned short*)&h0; hv.y = *(unsigned short*)&h1;
  hv.z = *(unsigned short*)&h2; hv.w = *(unsigned short*)&h3;
  *(ushort4*)(dst + i) = hv;
}

// ============= fp16 1-MMA GEMM: C[M,N] = A[M,K] * B[N,K]^T ================
// 128x128 CTA tile, 8 warps (4Mx2N), 3-stage cp.async, 2 CTAs/SM.
constexpr int ROWB  = 80;
constexpr int TILEB = 128 * ROWB;         // 10240
constexpr int STGB  = 2 * TILEB;          // A | B per stage
constexpr int SMEM_GEMM = 3 * STGB;       // 61440

__global__ void __launch_bounds__(256, 2) gemm_mma(
    const __half* __restrict__ A, const __half* __restrict__ B,
    float* __restrict__ C, int M, int N, int K)
{
  char* smem = dyn_smem;
  const uint32_t sb0 = smem_to_u32(smem);
  const int tid = threadIdx.x;
  const int lane = tid & 31, wid = tid >> 5;
  const int bm = blockIdx.y * 128, bn = blockIdx.x * 128;
  const int wm = (wid >> 1) * 32, wn = (wid & 1) * 64;

  float acc[2][8][4];
  #pragma unroll
  for (int i = 0; i < 2; ++i)
    #pragma unroll
    for (int j = 0; j < 8; ++j)
      #pragma unroll
      for (int q = 0; q < 4; ++q) acc[i][j][q] = 0.0f;

  auto load_tile = [&](int kt, int stg) {
    const uint32_t sb = sb0 + stg * STGB;
    const long kb = (long)kt * 32;
    #pragma unroll
    for (int i = 0; i < 2; ++i) {
      int o = tid + 256 * i;
      int row = o >> 2, seg = o & 3;
      uint32_t soff = row * ROWB + seg * 16;
      cp16(sb + soff,         A + (long)(bm + row) * K + kb + seg * 8);
      cp16(sb + TILEB + soff, B + (long)(bn + row) * K + kb + seg * 8);
    }
    asm volatile("cp.async.commit_group;" ::: "memory");
  };

  const int KT = K >> 5;
  load_tile(0, 0);
  load_tile(1, 1);
  for (int kt = 0; kt < KT; ++kt) {
    const int stg = kt % 3;
    if (kt < KT - 1) {
      asm volatile("cp.async.wait_group 1;" ::: "memory");
    } else {
      asm volatile("cp.async.wait_group 0;" ::: "memory");
    }
    __syncthreads();
    if (kt + 2 < KT) load_tile(kt + 2, (kt + 2) % 3);
    const uint32_t sb = sb0 + stg * STGB;
    #pragma unroll
    for (int h = 0; h < 2; ++h) {
      uint32_t ah[2][4];
      #pragma unroll
      for (int mi = 0; mi < 2; ++mi) {
        uint32_t ad = sb + (uint32_t)(wm + mi*16 + (lane & 15)) * ROWB
                         + h*32 + (lane >> 4) * 16;
        ldsm4(ah[mi], ad);
      }
      #pragma unroll
      for (int nj2 = 0; nj2 < 4; ++nj2) {
        uint32_t bd = sb + TILEB
          + (uint32_t)(wn + nj2*16 + (lane & 7) + ((lane >> 4) << 3)) * ROWB
          + h*32 + ((lane >> 3) & 1) * 16;
        uint32_t bf[4];
        ldsm4(bf, bd);
        #pragma unroll
        for (int mi = 0; mi < 2; ++mi)
          #pragma unroll
          for (int s = 0; s < 2; ++s)
            mma16816h(acc[mi][nj2*2+s], ah[mi], bf[2*s], bf[2*s+1]);
      }
    }
  }

  #pragma unroll
  for (int mi = 0; mi < 2; ++mi) {
    int row = bm + wm + mi*16 + (lane >> 2);
    #pragma unroll
    for (int nj = 0; nj < 8; ++nj) {
      int col = bn + wn + nj*8 + (lane & 3)*2;
      if (col < N) {
        *(float2*)(C + (long)row * N + col) =
            make_float2(acc[mi][nj][0], acc[mi][nj][1]);
        *(float2*)(C + (long)(row + 8) * N + col) =
            make_float2(acc[mi][nj][2], acc[mi][nj][3]);
      }
    }
  }
}

// ============= K2: conv1d + SiLU + softplus(dt), 8 rows per block =========
constexpr int CTL = 8;
__global__ void __launch_bounds__(256) k_conv(
    const float* __restrict__ conv_w, const float* __restrict__ conv_b,
    const float* __restrict__ dt_bias)
{
  const int blk = blockIdx.x;
  const int b = blk / (cL / CTL), lt = blk % (cL / CTL);
  const int l0 = lt * CTL;
  const int tid = threadIdx.x;
  const size_t rb = ((size_t)(b * cL + l0)) * cDP + cDS;
  const size_t ob = ((size_t)(b * cL + l0)) * cCD;
  #pragma unroll 1
  for (int q = 0; q < 5; ++q) {
    int c4 = tid + q * 256;
    if (c4 >= cCD / 4) break;
    int c = c4 * 4;
    float4 wa = *(const float4*)(conv_w + c*3);
    float4 wb = *(const float4*)(conv_w + c*3 + 4);
    float4 wc = *(const float4*)(conv_w + c*3 + 8);
    float4 bs = *(const float4*)(conv_b + c);
    float4 xr[CTL + 2];
    #pragma unroll
    for (int r = 0; r < CTL + 2; ++r) {
      int gl = l0 - 2 + r;
      xr[r] = (gl >= 0) ? *(const float4*)(&g_zx[rb + (size_t)(r - 2) * cDP + c])
                        : make_float4(0.f, 0.f, 0.f, 0.f);
    }
    #pragma unroll
    for (int t = 0; t < CTL; ++t) {
      float4 x2 = xr[t], x1 = xr[t + 1], x0 = xr[t + 2];
      float4 s;
      s.x = bs.x + x2.x*wa.x + x1.x*wa.y + x0.x*wa.z;
      s.y = bs.y + x2.y*wa.w + x1.y*wb.x + x0.y*wb.y;
      s.z = bs.z + x2.z*wb.z + x1.z*wb.w + x0.z*wc.x;
      s.w = bs.w + x2.w*wc.y + x1.w*wc.z + x0.w*wc.w;
      s.x *= fsig(s.x); s.y *= fsig(s.y); s.z *= fsig(s.z); s.w *= fsig(s.w);
      *(float4*)(&g_xbc[ob + (size_t)t * cCD + c]) = s;
    }
  }
  #pragma unroll
  for (int i = 0; i < 2; ++i) {
    int idx = tid + i * 256;
    int hh = idx & 63, t = idx >> 6;
    float v = g_zx[((size_t)(b * cL + l0 + t)) * cDP + (cDP - cNH) + hh]
              + dt_bias[hh];
    float sp = (v > 15.0f) ? v : log1pf(expf(v));
    g_dt[((size_t)b * cNH + hh) * cL + l0 + t] = sp;
  }
}

// ============= K3: per-chunk inclusive cumsum of dt*A =====================
__global__ void __launch_bounds__(128) k_scan(const float* __restrict__ A_log)
{
  const int h = blockIdx.x, c = blockIdx.y, b = blockIdx.z;
  const int l = threadIdx.x;
  const float ah = -expf(A_log[h]);
  const size_t base = ((size_t)b * cNH + h) * cL + c * cCK;
  __shared__ float s[128];
  s[l] = g_dt[base + l] * ah;
  __syncthreads();
  #pragma unroll
  for (int off = 1; off < 128; off <<= 1) {
    float t = (l >= off) ? s[l - off] : 0.0f;
    __syncthreads();
    s[l] += t;
    __syncthreads();
  }
  g_ac[base + l] = s[l];
  if (l == 127) g_T[((size_t)b * cNH + h) * cNC + c] = s[127];
}

// ============= K4: chunk states (fp16 mma, single-B) ======================
constexpr int S_AS  = 136;
constexpr int S_BS  = 72;
constexpr int S_Ao  = 0;
constexpr int S_Bo  = 128 * S_AS * 2;          // 34816
constexpr int S_SCo = S_Bo + 128 * S_BS * 2;   // 53248
constexpr int S_SMEM = S_SCo + 512;            // 53760

__global__ void __launch_bounds__(256, 2) k_states()
{
  char* sm = dyn_smem;
  __half* Ap = (__half*)(sm + S_Ao);
  __half* Bp = (__half*)(sm + S_Bo);
  float* sc = (float*)(sm + S_SCo);
  const uint32_t sb = smem_to_u32(sm);
  const int h = blockIdx.x, c = blockIdx.y, b = blockIdx.z;
  const int tid = threadIdx.x, lane = tid & 31, wid = tid >> 5;
  const size_t rowbase = ((size_t)(b * cL + c * cCK)) * cCD;
  const size_t acb = ((size_t)b * cNH + h) * cL + c * cCK;
  if (tid < 128) {
    float T = g_T[((size_t)b * cNH + h) * cNC + c];
    sc[tid] = g_dt[acb + tid] * fexp(T - g_ac[acb + tid]);
  }
  __syncthreads();
  #pragma unroll 1
  for (int q = 0; q < 16; ++q) {
    int i = (tid + q * 256) * 4;
    int l = i >> 7, n = i & 127;
    float4 v = *(const float4*)&g_xbc[rowbase + (size_t)l * cCD + cDS + n];
    float vv[4] = {v.x, v.y, v.z, v.w};
    #pragma unroll
    for (int j = 0; j < 4; ++j)
      Ap[l * S_AS + n + j] = __float2half_rn(vv[j]);
  }
  #pragma unroll 1
  for (int q = 0; q < 8; ++q) {
    int i = (tid + q * 256) * 4;
    int l = i >> 6, p = i & 63;
    float4 x = *(const float4*)&g_xbc[rowbase + (size_t)l * cCD + h * cHD + p];
    float s = sc[l];
    float xv[4] = {x.x * s, x.y * s, x.z * s, x.w * s};
    #pragma unroll
    for (int j = 0; j < 4; ++j)
      Bp[l * S_BS + p + j] = __float2half_rn(xv[j]);
  }
  __syncthreads();

  const int wm = (wid >> 1) * 32, wn = (wid & 1) * 32;
  float acc[2][4][4];
  #pragma unroll
  for (int mi = 0; mi < 2; ++mi)
    #pragma unroll
    for (int nj = 0; nj < 4; ++nj)
      #pragma unroll
      for (int q = 0; q < 4; ++q) acc[mi][nj][q] = 0.0f;

  #pragma unroll
  for (int kk = 0; kk < 8; ++kk) {
    uint32_t ah4[2][4];
    #pragma unroll
    for (int mi = 0; mi < 2; ++mi) {
      uint32_t ad = sb + S_Ao
        + (uint32_t)(kk*16 + (lane & 7) + ((lane >> 4) << 3)) * (S_AS * 2)
        + (uint32_t)(wm + mi*16 + (lane & 8)) * 2;
      ldsm4t(ah4[mi], ad);
    }
    uint32_t bf[2][4];
    #pragma unroll
    for (int nj2 = 0; nj2 < 2; ++nj2) {
      uint32_t bd = sb + S_Bo
        + (uint32_t)(kk*16 + (lane & 15)) * (S_BS * 2)
        + (uint32_t)(wn + nj2*16 + ((lane >> 4) << 3)) * 2;
      ldsm4t(bf[nj2], bd);
    }
    #pragma unroll
    for (int nj2 = 0; nj2 < 2; ++nj2)
      #pragma unroll
      for (int mi = 0; mi < 2; ++mi)
        #pragma unroll
        for (int s2 = 0; s2 < 2; ++s2)
          mma16816h(acc[mi][nj2*2+s2], ah4[mi], bf[nj2][2*s2], bf[nj2][2*s2+1]);
  }

  const size_t ob = (((size_t)b * cNC + c) * cNH + h) * (cST * cHD);
  #pragma unroll
  for (int mi = 0; mi < 2; ++mi) {
    int row = wm + mi*16 + (lane >> 2);
    #pragma unroll
    for (int nj = 0; nj < 4; ++nj) {
      int col = wn + nj*8 + (lane & 3)*2;
      *(float2*)&g_cs[ob + (size_t)row * cHD + col] =
          make_float2(acc[mi][nj][0], acc[mi][nj][1]);
      *(float2*)&g_cs[ob + (size_t)(row + 8) * cHD + col] =
          make_float2(acc[mi][nj][2], acc[mi][nj][3]);
    }
  }
}

// ============= K5: inter-chunk carry scan (4-way state split) =============
__global__ void __launch_bounds__(256) k_carry()
{
  const int blk = blockIdx.x;            // cB*cNH*4
  const int bh = blk >> 2, qt = blk & 3;
  const int b = bh >> 6, h = bh & 63;
  const int off = qt * 2048;
  const int tid = threadIdx.x;
  float carry[8];
  #pragma unroll
  for (int j = 0; j < 8; ++j) carry[j] = 0.0f;
  for (int c = 0; c < cNC; ++c) {
    if (c > 0) {
      float eT = fexp(g_T[(size_t)bh * cNC + (c - 1)]);
      const size_t inb = (((size_t)b * cNC + (c - 1)) * cNH + h) * (cST * cHD) + off;
      #pragma unroll
      for (int j = 0; j < 8; ++j)
        carry[j] = carry[j] * eT + g_cs[inb + tid + j * 256];
    }
    const size_t ob = (((size_t)b * cNC + c) * cNH + h) * (cST * cHD) + off;
    #pragma unroll
    for (int j = 0; j < 8; ++j)
      g_pv[ob + tid + j * 256] = carry[j];
  }
}

// ============= K5.5: unmasked G = C * B^T per (b,c) =======================
__global__ void __launch_bounds__(256) k_gmat()
{
  float* smf = (float*)dyn_smem;
  float* Ct = smf;
  float* Bt = smf + 128 * 132;
  const int c = blockIdx.x, b = blockIdx.y;
  const int tid = threadIdx.x;
  const size_t rowbase = ((size_t)(b * cL + c * cCK)) * cCD;
  #pragma unroll 1
  for (int q = 0; q < 16; ++q) {
    int i = tid + q * 256;
    int l = i >> 5, nq = i & 31;
    const float* src = &g_xbc[rowbase + (size_t)l * cCD];
    float4 cv = *(const float4*)(src + cDS + cST + nq * 4);
    float4 bv = *(const float4*)(src + cDS + nq * 4);
    int n = nq * 4;
    Ct[(n+0)*132 + l] = cv.x; Ct[(n+1)*132 + l] = cv.y;
    Ct[(n+2)*132 + l] = cv.z; Ct[(n+3)*132 + l] = cv.w;
    Bt[(n+0)*132 + l] = bv.x; Bt[(n+1)*132 + l] = bv.y;
    Bt[(n+2)*132 + l] = bv.z; Bt[(n+3)*132 + l] = bv.w;
  }
  __syncthreads();
  const int ty = tid >> 4, tx = tid & 15;
  const int l0 = ty * 8, s0 = tx * 8;
  float accG[8][8] = {};
  for (int n = 0; n < cST; ++n) {
    float4 a0 = *(const float4*)&Ct[n*132 + l0];
    float4 a1 = *(const float4*)&Ct[n*132 + l0 + 4];
    float4 b0 = *(const float4*)&Bt[n*132 + s0];
    float4 b1 = *(const float4*)&Bt[n*132 + s0 + 4];
    float a[8]  = {a0.x, a0.y, a0.z, a0.w, a1.x, a1.y, a1.z, a1.w};
    float bb[8] = {b0.x, b0.y, b0.z, b0.w, b1.x, b1.y, b1.z, b1.w};
    #pragma unroll
    for (int i = 0; i < 8; ++i)
      #pragma unroll
      for (int j = 0; j < 8; ++j) accG[i][j] += a[i] * bb[j];
  }
  const size_t gb = ((size_t)(b * cNC + c)) * (cCK * cCK);
  #pragma unroll
  for (int i = 0; i < 8; ++i) {
    #pragma unroll
    for (int j = 0; j < 4; ++j) {
      *(float2*)&g_gm[gb + (size_t)(l0 + i) * cCK + s0 + 2*j] =
          make_float2(accG[i][2*j], accG[i][2*j+1]);
    }
  }
}

// ============= K6: SSD Y kernel (fp16 mma single-B, 2 passes) =============
constexpr int Y_AS = 136;
constexpr int Y_BS = 72;
constexpr int Y_Ao  = 0;
constexpr int Y_Bo  = 128 * Y_AS * 2;          // 34816
constexpr int Y_ACS = Y_Bo + 128 * Y_BS * 2;   // 53248
constexpr int Y_DTS = Y_ACS + 512;             // 53760
constexpr int Y_SMEM = Y_DTS + 512;            // 54272

__global__ void __launch_bounds__(256, 2) k_ssd_y(const float* __restrict__ Dv)
{
  char* sm = dyn_smem;
  __half* Ap = (__half*)(sm + Y_Ao);
  __half* Bp = (__half*)(sm + Y_Bo);
  float* acs = (float*)(sm + Y_ACS);
  float* dts = (float*)(sm + Y_DTS);
  const uint32_t sb = smem_to_u32(sm);
  const int h = blockIdx.x, c = blockIdx.y, b = blockIdx.z;
  const int tid = threadIdx.x, lane = tid & 31, wid = tid >> 5;
  const size_t rowbase = ((size_t)(b * cL + c * cCK)) * cCD;
  const size_t acb = ((size_t)b * cNH + h) * cL + c * cCK;
  if (tid < 128) { acs[tid] = g_ac[acb + tid]; dts[tid] = g_dt[acb + tid]; }
  __syncthreads();

  const size_t gb = ((size_t)(b * cNC + c)) * (cCK * cCK);
  #pragma unroll 1
  for (int q = 0; q < 16; ++q) {
    int i = (tid + q * 256) * 4;
    int l = i >> 7, s = i & 127;
    float4 g = *(const float4*)&g_gm[gb + i];
    float al = acs[l];
    float gv[4] = {g.x, g.y, g.z, g.w};
    #pragma unroll
    for (int j = 0; j < 4; ++j) {
      int ss = s + j;
      float m = (ss <= l) ? fexp(al - acs[ss]) : 0.0f;
      Ap[l * Y_AS + ss] = __float2half_rn(gv[j] * m);
    }
  }
  #pragma unroll 1
  for (int q = 0; q < 8; ++q) {
    int i = (tid + q * 256) * 4;
    int s = i >> 6, p = i & 63;
    float4 x = *(const float4*)&g_xbc[rowbase + (size_t)s * cCD + h * cHD + p];
    float dv = dts[s];
    float xv[4] = {x.x * dv, x.y * dv, x.z * dv, x.w * dv};
    #pragma unroll
    for (int j = 0; j < 4; ++j)
      Bp[s * Y_BS + p + j] = __float2half_rn(xv[j]);
  }
  __syncthreads();

  const int wm = (wid >> 1) * 32, wn = (wid & 1) * 32;
  float acc[2][4][4];
  #pragma unroll
  for (int mi = 0; mi < 2; ++mi)
    #pragma unroll
    for (int nj = 0; nj < 4; ++nj)
      #pragma unroll
      for (int q = 0; q < 4; ++q) acc[mi][nj][q] = 0.0f;

  auto mma_pass = [&]() {
    #pragma unroll
    for (int kk = 0; kk < 8; ++kk) {
      uint32_t ah4[2][4];
      #pragma unroll
      for (int mi = 0; mi < 2; ++mi) {
        uint32_t ad = sb + Y_Ao
          + (uint32_t)(wm + mi*16 + (lane & 15)) * (Y_AS * 2)
          + kk*32 + (lane >> 4) * 16;
        ldsm4(ah4[mi], ad);
      }
      uint32_t bf[2][4];
      #pragma unroll
      for (int nj2 = 0; nj2 < 2; ++nj2) {
        uint32_t bd = sb + Y_Bo
          + (uint32_t)(kk*16 + (lane & 15)) * (Y_BS * 2)
          + (uint32_t)(wn + nj2*16 + ((lane >> 4) << 3)) * 2;
        ldsm4t(bf[nj2], bd);
      }
      #pragma unroll
      for (int nj2 = 0; nj2 < 2; ++nj2)
        #pragma unroll
        for (int mi = 0; mi < 2; ++mi)
          #pragma unroll
          for (int s2 = 0; s2 < 2; ++s2)
            mma16816h(acc[mi][nj2*2+s2], ah4[mi], bf[nj2][2*s2], bf[nj2][2*s2+1]);
    }
  };
  mma_pass();          // Y += Gm @ X'
  __syncthreads();

  #pragma unroll 1
  for (int q = 0; q < 16; ++q) {
    int i = (tid + q * 256) * 4;
    int l = i >> 7, n = i & 127;
    float4 cv = *(const float4*)&g_xbc[rowbase + (size_t)l * cCD + cDS + cST + n];
    float e = fexp(acs[l]);
    float cvv[4] = {cv.x * e, cv.y * e, cv.z * e, cv.w * e};
    #pragma unroll
    for (int j = 0; j < 4; ++j)
      Ap[l * Y_AS + n + j] = __float2half_rn(cvv[j]);
  }
  {
    const size_t pb = (((size_t)b * cNC + c) * cNH + h) * (cST * cHD);
    #pragma unroll 1
    for (int q = 0; q < 8; ++q) {
      int i = (tid + q * 256) * 4;
      int n = i >> 6, p = i & 63;
      float4 pv = *(const float4*)&g_pv[pb + i];
      float pvv[4] = {pv.x, pv.y, pv.z, pv.w};
      #pragma unroll
      for (int j = 0; j < 4; ++j)
        Bp[n * Y_BS + p + j] = __float2half_rn(pvv[j]);
    }
  }
  __syncthreads();
  mma_pass();          // Y += Ce @ P

  const float Dh = Dv[h];
  #pragma unroll
  for (int mi = 0; mi < 2; ++mi) {
    int row = wm + mi*16 + (lane >> 2);
    #pragma unroll
    for (int nj = 0; nj < 4; ++nj) {
      int col = wn + nj*8 + (lane & 3)*2;
      float2 x0 = *(const float2*)&g_xbc[rowbase + (size_t)row * cCD + h * cHD + col];
      float2 x1 = *(const float2*)&g_xbc[rowbase + (size_t)(row+8) * cCD + h * cHD + col];
      size_t y0 = ((size_t)(b * cL + c * cCK + row)) * cDS + h * cHD + col;
      size_t y1 = ((size_t)(b * cL + c * cCK + row + 8)) * cDS + h * cHD + col;
      *(float2*)&g_y[y0] = make_float2(acc[mi][nj][0] + Dh * x0.x,
                                       acc[mi][nj][1] + Dh * x0.y);
      *(float2*)&g_y[y1] = make_float2(acc[mi][nj][2] + Dh * x1.x,
                                       acc[mi][nj][3] + Dh * x1.y);
    }
  }
}

// ============= K7: gate (silu(z)) + RMSNorm + fp16 cvt (fused) ============
__global__ void __launch_bounds__(256) k_gate_norm(const float* __restrict__ norm_w)
{
  const int row = blockIdx.x;
  const int tid = threadIdx.x;
  const size_t zb = (size_t)row * cDP;
  const size_t yb = (size_t)row * cDS;
  float v[16];
  float ss = 0.0f;
  #pragma unroll
  for (int q = 0; q < 16; ++q) {
    int i = tid + q * 256;
    float z = g_zx[zb + i];
    float y = g_y[yb + i];
    float t = y * z * fsig(z);
    v[q] = t;
    ss += t * t;
  }
  #pragma unroll
  for (int o = 16; o > 0; o >>= 1) ss += __shfl_xor_sync(0xffffffffu, ss, o);
  __shared__ float red[8];
  if ((tid & 31) == 0) red[tid >> 5] = ss;
  __syncthreads();
  float tot = 0.0f;
  #pragma unroll
  for (int j = 0; j < 8; ++j) tot += red[j];
  const float scale = rsqrtf(tot / (float)cDS + cEPS);
  #pragma unroll
  for (int q = 0; q < 16; ++q) {
    int i = tid + q * 256;
    float t = v[q] * scale * norm_w[i];
    __half hh = __float2half_rn(t);
    g_ah[yb + i] = *(unsigned short*)&hh;
  }
}

// ============= K9: out + reverse(out) =====================================
__global__ void __launch_bounds__(256) k_revadd(float* __restrict__ out)
{
  const int idx4 = blockIdx.x * 256 + threadIdx.x;
  const int tot4 = cB * cL * cDM / 4;
  if (idx4 >= tot4) return;
  const int i = idx4 * 4;
  const int b = i / (cL * cDM);
  const int r = i - b * (cL * cDM);
  const int l = r / cDM;
  const int d = r - l * cDM;
  const size_t rev = ((size_t)b * cL + (cL - 1 - l)) * cDM + d;
  float4 a = *(const float4*)(&g_o[i]);
  float4 c = *(const float4*)(&g_o[rev]);
  a.x += c.x; a.y += c.y; a.z += c.z; a.w += c.w;
  *(float4*)(out + i) = a;
}

// ==========================================================================
extern "C" void kernel_launch(void* const* d_in, const int* in_sizes, int n_in,
                              void* d_out, int out_size) {
  const float* u       = (const float*)d_in[0];
  const float* W_in    = (const float*)d_in[1];
  const float* conv_w  = (const float*)d_in[2];
  const float* conv_b  = (const float*)d_in[3];
  const float* dt_bias = (const float*)d_in[4];
  const float* A_log   = (const float*)d_in[5];
  const float* Dv      = (const float*)d_in[6];
  const float* norm_w  = (const float*)d_in[7];
  const float* W_out   = (const float*)d_in[8];
  float* out = (float*)d_out;

  float* zx; cudaGetSymbolAddress((void**)&zx, g_zx);
  float* ob; cudaGetSymbolAddress((void**)&ob, g_o);
  unsigned short *ah, *bh, *b2h;
  cudaGetSymbolAddress((void**)&ah,  g_ah);
  cudaGetSymbolAddress((void**)&bh,  g_bh);
  cudaGetSymbolAddress((void**)&b2h, g_b2h);

  cudaFuncSetAttribute(gemm_mma, cudaFuncAttributeMaxDynamicSharedMemorySize,
                       SMEM_GEMM);
  cudaFuncSetAttribute(k_gmat, cudaFuncAttributeMaxDynamicSharedMemorySize,
                       2 * 128 * 132 * 4);
  cudaFuncSetAttribute(k_states, cudaFuncAttributeMaxDynamicSharedMemorySize,
                       S_SMEM);
  cudaFuncSetAttribute(k_ssd_y, cudaFuncAttributeMaxDynamicSharedMemorySize,
                       Y_SMEM);

  const int M = cB * cL;   // 4096

  // --- prep: u -> fp16; W_in (padded), W_out -> fp16 ---
  {
    long totA = (long)M * cDM;
    k_cvt_h<<<(unsigned)((totA/4 + 255)/256), 256>>>(u, ah, totA);
    long totB = (long)cNPAD1 * cDM;
    k_cvt_h_pad<<<(unsigned)((totB/4 + 255)/256), 256>>>(W_in, bh, cDP, cDM, totB);
    long totB2 = (long)cDM * cDS;
    k_cvt_h<<<(unsigned)((totB2/4 + 255)/256), 256>>>(W_out, b2h, totB2);
  }
  // --- GEMM1: zx[4096, 8512] ---
  {
    dim3 grid(cNPAD1 / 128, M / 128);
    gemm_mma<<<grid, 256, SMEM_GEMM>>>(
        (const __half*)ah, (const __half*)bh, zx, M, cDP, cDM);
  }
  // --- conv + silu + dt ---
  k_conv<<<cB * cL / CTL, 256>>>(conv_w, conv_b, dt_bias);
  // --- per-chunk cumsum ---
  { dim3 grid(cNH, cNC, cB); k_scan<<<grid, 128>>>(A_log); }
  // --- chunk states (fp16 mma) ---
  { dim3 grid(cNH, cNC, cB); k_states<<<grid, 256, S_SMEM>>>(); }
  // --- carry scan (4-way split) ---
  k_carry<<<cB * cNH * 4, 256>>>();
  // --- unmasked G ---
  { dim3 grid(cNC, cB); k_gmat<<<grid, 256, 2 * 128 * 132 * 4>>>(); }
  // --- Y (fp16 mma) ---
  { dim3 grid(cNH, cNC, cB); k_ssd_y<<<grid, 256, Y_SMEM>>>(Dv); }
  // --- gate + rmsnorm + fp16 cvt (fused) ---
  k_gate_norm<<<cB * cL, 256>>>(norm_w);
  // --- GEMM2: o[4096, 2048] ---
  {
    dim3 grid(cDM / 128, M / 128);
    gemm_mma<<<grid, 256, SMEM_GEMM>>>(
        (const __half*)ah, (const __half*)b2h, ob, M, cDM, cDS);
  }
  // --- out + reverse(out) ---
  k_revadd<<<(cB * cL * cDM / 4 + 255) / 256, 256>>>(out);
}

// round 16
// speedup vs baseline: 1.6122x; 1.0050x over previous
#include <cuda_runtime.h>
#include <cuda_bf16.h>
#include <cuda_fp16.h>
#include <cstdint>

#define DEVFN static __device__ __forceinline__

constexpr int cB  = 2;
constexpr int cL  = 2048;
constexpr int cDM = 2048;
constexpr int cDS = 4096;
constexpr int cST = 128;
constexpr int cNH = 64;
constexpr int cHD = 64;
constexpr int cCK = 128;
constexpr int cNC = cL / cCK;        // 16
constexpr int cDP = 2*cDS + 2*cST + cNH;   // 8512
constexpr int cCD = cDS + 2*cST;           // 4352
constexpr float cEPS = 1e-5f;

constexpr int cNPAD1 = 8576;         // padded N for GEMM1 (67 * 128)

// ---------------- scratch ----------
__device__ float g_zx [(size_t)cB*cL*cDP];
__device__ float g_xbc[(size_t)cB*cL*cCD];
__device__ float g_dt [(size_t)cB*cNH*cL];
__device__ float g_ac [(size_t)cB*cNH*cL];
__device__ float g_T  [(size_t)cB*cNH*cNC];
__device__ float g_cs [(size_t)cB*cNC*cNH*cST*cHD];
__device__ float g_pv [(size_t)cB*cNC*cNH*cST*cHD];
__device__ unsigned short g_gmh[(size_t)cB*cNC*cCK*cCK];   // G in fp16
__device__ float g_y  [(size_t)cB*cL*cDS];
__device__ float g_o  [(size_t)cB*cL*cDM];
__device__ unsigned short g_ah [(size_t)4096*4096];
__device__ unsigned short g_bh [(size_t)cNPAD1*2048];
__device__ unsigned short g_b2h[(size_t)cDM*cDS];

// ---------------- math helpers --------------------------------------------
DEVFN float fexp(float x) {
  float t = x * 1.44269504088896340736f;
  t = fminf(fmaxf(t, -126.0f), 126.0f);
  float fi = rintf(t);
  float f  = t - fi;
  float p = 1.5403530393381610e-4f;
  p = fmaf(p, f, 1.3333558146428443e-3f);
  p = fmaf(p, f, 9.6181291076284772e-3f);
  p = fmaf(p, f, 5.5504108664821580e-2f);
  p = fmaf(p, f, 2.4022650695910071e-1f);
  p = fmaf(p, f, 6.9314718055994531e-1f);
  p = fmaf(p, f, 1.0f);
  int i = (int)fi;
  return __int_as_float((i + 127) << 23) * p;
}
DEVFN float fsig(float x) { return 1.0f / (1.0f + fexp(-x)); }

DEVFN uint32_t smem_to_u32(const void* p) {
  uint32_t a;
  asm("{ .reg .u64 t; cvta.to.shared.u64 t, %1; cvt.u32.u64 %0, t; }"
      : "=r"(a) : "l"(p));
  return a;
}
DEVFN void cp16(uint32_t saddr, const void* gptr) {
  asm volatile("cp.async.cg.shared.global [%0], [%1], 16;"
               :: "r"(saddr), "l"(gptr) : "memory");
}
DEVFN void ldsm4(uint32_t (&r)[4], uint32_t a) {
  asm volatile("ldmatrix.sync.aligned.m8n8.x4.shared.b16 {%0,%1,%2,%3}, [%4];"
    : "=r"(r[0]), "=r"(r[1]), "=r"(r[2]), "=r"(r[3]) : "r"(a));
}
DEVFN void ldsm4t(uint32_t (&r)[4], uint32_t a) {
  asm volatile("ldmatrix.sync.aligned.m8n8.x4.trans.shared.b16 {%0,%1,%2,%3}, [%4];"
    : "=r"(r[0]), "=r"(r[1]), "=r"(r[2]), "=r"(r[3]) : "r"(a));
}
DEVFN void mma16816h(float (&d)[4], const uint32_t (&a)[4], uint32_t b0, uint32_t b1) {
  asm volatile("mma.sync.aligned.m16n8k16.row.col.f32.f16.f16.f32 "
    "{%0,%1,%2,%3},{%4,%5,%6,%7},{%8,%9},{%0,%1,%2,%3};"
    : "+f"(d[0]), "+f"(d[1]), "+f"(d[2]), "+f"(d[3])
    : "r"(a[0]), "r"(a[1]), "r"(a[2]), "r"(a[3]), "r"(b0), "r"(b1));
}

extern __shared__ char dyn_smem[];

// ============= K0a: fp32 -> fp16 ==========================================
__global__ void __launch_bounds__(256) k_cvt_h(
    const float* __restrict__ src, unsigned short* __restrict__ dst, long tot)
{
  long i = ((long)blockIdx.x * 256 + threadIdx.x) * 4;
  if (i >= tot) return;
  float4 v = *(const float4*)(src + i);
  __half h0 = __float2half_rn(v.x), h1 = __float2half_rn(v.y);
  __half h2 = __float2half_rn(v.z), h3 = __float2half_rn(v.w);
  ushort4 hv;
  hv.x = *(unsigned short*)&h0; hv.y = *(unsigned short*)&h1;
  hv.z = *(unsigned short*)&h2; hv.w = *(unsigned short*)&h3;
  *(ushort4*)(dst + i) = hv;
}

// ============= K0b: fp32 -> fp16 with row zero-padding ====================
__global__ void __launch_bounds__(256) k_cvt_h_pad(
    const float* __restrict__ src, unsigned short* __restrict__ dst,
    int srcRows, int K, long tot)
{
  long i = ((long)blockIdx.x * 256 + threadIdx.x) * 4;
  if (i >= tot) return;
  long row = i / K;
  float4 v = make_float4(0.f, 0.f, 0.f, 0.f);
  if (row < srcRows) v = *(const float4*)(src + i);
  __half h0 = __float2half_rn(v.x), h1 = __float2half_rn(v.y);
  __half h2 = __float2half_rn(v.z), h3 = __float2half_rn(v.w);
  ushort4 hv;
  hv.x = *(unsigned short*)&h0; hv.y = *(unsigned short*)&h1;
  hv.z = *(unsigned short*)&h2; hv.w = *(unsigned short*)&h3;
  *(ushort4*)(dst + i) = hv;
}

// ============= fp16 1-MMA GEMM: C[M,N] = A[M,K] * B[N,K]^T ================
constexpr int ROWB  = 80;
constexpr int TILEB = 128 * ROWB;         // 10240
constexpr int STGB  = 2 * TILEB;
constexpr int SMEM_GEMM = 3 * STGB;       // 61440

__global__ void __launch_bounds__(256, 2) gemm_mma(
    const __half* __restrict__ A, const __half* __restrict__ B,
    float* __restrict__ C, int M, int N, int K)
{
  char* smem = dyn_smem;
  const uint32_t sb0 = smem_to_u32(smem);
  const int tid = threadIdx.x;
  const int lane = tid & 31, wid = tid >> 5;
  const int bm = blockIdx.y * 128, bn = blockIdx.x * 128;
  const int wm = (wid >> 1) * 32, wn = (wid & 1) * 64;

  float acc[2][8][4];
  #pragma unroll
  for (int i = 0; i < 2; ++i)
    #pragma unroll
    for (int j = 0; j < 8; ++j)
      #pragma unroll
      for (int q = 0; q < 4; ++q) acc[i][j][q] = 0.0f;

  auto load_tile = [&](int kt, int stg) {
    const uint32_t sb = sb0 + stg * STGB;
    const long kb = (long)kt * 32;
    #pragma unroll
    for (int i = 0; i < 2; ++i) {
      int o = tid + 256 * i;
      int row = o >> 2, seg = o & 3;
      uint32_t soff = row * ROWB + seg * 16;
      cp16(sb + soff,         A + (long)(bm + row) * K + kb + seg * 8);
      cp16(sb + TILEB + soff, B + (long)(bn + row) * K + kb + seg * 8);
    }
    asm volatile("cp.async.commit_group;" ::: "memory");
  };

  const int KT = K >> 5;
  load_tile(0, 0);
  load_tile(1, 1);
  for (int kt = 0; kt < KT; ++kt) {
    const int stg = kt % 3;
    if (kt < KT - 1) {
      asm volatile("cp.async.wait_group 1;" ::: "memory");
    } else {
      asm volatile("cp.async.wait_group 0;" ::: "memory");
    }
    __syncthreads();
    if (kt + 2 < KT) load_tile(kt + 2, (kt + 2) % 3);
    const uint32_t sb = sb0 + stg * STGB;
    #pragma unroll
    for (int h = 0; h < 2; ++h) {
      uint32_t ah[2][4];
      #pragma unroll
      for (int mi = 0; mi < 2; ++mi) {
        uint32_t ad = sb + (uint32_t)(wm + mi*16 + (lane & 15)) * ROWB
                         + h*32 + (lane >> 4) * 16;
        ldsm4(ah[mi], ad);
      }
      #pragma unroll
      for (int nj2 = 0; nj2 < 4; ++nj2) {
        uint32_t bd = sb + TILEB
          + (uint32_t)(wn + nj2*16 + (lane & 7) + ((lane >> 4) << 3)) * ROWB
          + h*32 + ((lane >> 3) & 1) * 16;
        uint32_t bf[4];
        ldsm4(bf, bd);
        #pragma unroll
        for (int mi = 0; mi < 2; ++mi)
          #pragma unroll
          for (int s = 0; s < 2; ++s)
            mma16816h(acc[mi][nj2*2+s], ah[mi], bf[2*s], bf[2*s+1]);
      }
    }
  }

  #pragma unroll
  for (int mi = 0; mi < 2; ++mi) {
    int row = bm + wm + mi*16 + (lane >> 2);
    #pragma unroll
    for (int nj = 0; nj < 8; ++nj) {
      int col = bn + wn + nj*8 + (lane & 3)*2;
      if (col < N) {
        *(float2*)(C + (long)row * N + col) =
            make_float2(acc[mi][nj][0], acc[mi][nj][1]);
        *(float2*)(C + (long)(row + 8) * N + col) =
            make_float2(acc[mi][nj][2], acc[mi][nj][3]);
      }
    }
  }
}

// ============= K2: conv1d + SiLU + softplus(dt), 8 rows per block =========
constexpr int CTL = 8;
__global__ void __launch_bounds__(256) k_conv(
    const float* __restrict__ conv_w, const float* __restrict__ conv_b,
    const float* __restrict__ dt_bias)
{
  const int blk = blockIdx.x;
  const int b = blk / (cL / CTL), lt = blk % (cL / CTL);
  const int l0 = lt * CTL;
  const int tid = threadIdx.x;
  const size_t rb = ((size_t)(b * cL + l0)) * cDP + cDS;
  const size_t ob = ((size_t)(b * cL + l0)) * cCD;
  #pragma unroll 1
  for (int q = 0; q < 5; ++q) {
    int c4 = tid + q * 256;
    if (c4 >= cCD / 4) break;
    int c = c4 * 4;
    float4 wa = *(const float4*)(conv_w + c*3);
    float4 wb = *(const float4*)(conv_w + c*3 + 4);
    float4 wc = *(const float4*)(conv_w + c*3 + 8);
    float4 bs = *(const float4*)(conv_b + c);
    float4 xr[CTL + 2];
    #pragma unroll
    for (int r = 0; r < CTL + 2; ++r) {
      int gl = l0 - 2 + r;
      xr[r] = (gl >= 0) ? *(const float4*)(&g_zx[rb + (size_t)(r - 2) * cDP + c])
                        : make_float4(0.f, 0.f, 0.f, 0.f);
    }
    #pragma unroll
    for (int t = 0; t < CTL; ++t) {
      float4 x2 = xr[t], x1 = xr[t + 1], x0 = xr[t + 2];
      float4 s;
      s.x = bs.x + x2.x*wa.x + x1.x*wa.y + x0.x*wa.z;
      s.y = bs.y + x2.y*wa.w + x1.y*wb.x + x0.y*wb.y;
      s.z = bs.z + x2.z*wb.z + x1.z*wb.w + x0.z*wc.x;
      s.w = bs.w + x2.w*wc.y + x1.w*wc.z + x0.w*wc.w;
      s.x *= fsig(s.x); s.y *= fsig(s.y); s.z *= fsig(s.z); s.w *= fsig(s.w);
      *(float4*)(&g_xbc[ob + (size_t)t * cCD + c]) = s;
    }
  }
  #pragma unroll
  for (int i = 0; i < 2; ++i) {
    int idx = tid + i * 256;
    int hh = idx & 63, t = idx >> 6;
    float v = g_zx[((size_t)(b * cL + l0 + t)) * cDP + (cDP - cNH) + hh]
              + dt_bias[hh];
    float sp = (v > 15.0f) ? v : log1pf(expf(v));
    g_dt[((size_t)b * cNH + hh) * cL + l0 + t] = sp;
  }
}

// ============= K4: chunk states (fp16 mma, fused per-chunk scan) ==========
constexpr int S_AS  = 136;
constexpr int S_BS  = 72;
constexpr int S_Ao  = 0;
constexpr int S_Bo  = 128 * S_AS * 2;          // 34816
constexpr int S_SCo = S_Bo + 128 * S_BS * 2;   // 53248
constexpr int S_ACo = S_SCo + 512;             // 53760
constexpr int S_SMEM = S_ACo + 512;            // 54272

__global__ void __launch_bounds__(256, 2) k_states(const float* __restrict__ A_log)
{
  char* sm = dyn_smem;
  __half* Ap = (__half*)(sm + S_Ao);
  __half* Bp = (__half*)(sm + S_Bo);
  float* sc = (float*)(sm + S_SCo);
  float* sA = (float*)(sm + S_ACo);
  const uint32_t sb = smem_to_u32(sm);
  const int h = blockIdx.x, c = blockIdx.y, b = blockIdx.z;
  const int tid = threadIdx.x, lane = tid & 31, wid = tid >> 5;
  const size_t rowbase = ((size_t)(b * cL + c * cCK)) * cCD;
  const size_t acb = ((size_t)b * cNH + h) * cL + c * cCK;

  // --- fused per-chunk inclusive scan of dt*A ---
  const float ahv = -expf(A_log[h]);
  if (tid < 128) sA[tid] = g_dt[acb + tid] * ahv;
  __syncthreads();
  #pragma unroll
  for (int off = 1; off < 128; off <<= 1) {
    float t = 0.0f;
    if (tid < 128 && tid >= off) t = sA[tid - off];
    __syncthreads();
    if (tid < 128) sA[tid] += t;
    __syncthreads();
  }
  if (tid < 128) {
    float T = sA[127];
    g_ac[acb + tid] = sA[tid];
    if (tid == 127) g_T[((size_t)b * cNH + h) * cNC + c] = T;
    sc[tid] = g_dt[acb + tid] * fexp(T - sA[tid]);
  }
  __syncthreads();

  #pragma unroll 1
  for (int q = 0; q < 16; ++q) {
    int i = (tid + q * 256) * 4;
    int l = i >> 7, n = i & 127;
    float4 v = *(const float4*)&g_xbc[rowbase + (size_t)l * cCD + cDS + n];
    float vv[4] = {v.x, v.y, v.z, v.w};
    #pragma unroll
    for (int j = 0; j < 4; ++j)
      Ap[l * S_AS + n + j] = __float2half_rn(vv[j]);
  }
  #pragma unroll 1
  for (int q = 0; q < 8; ++q) {
    int i = (tid + q * 256) * 4;
    int l = i >> 6, p = i & 63;
    float4 x = *(const float4*)&g_xbc[rowbase + (size_t)l * cCD + h * cHD + p];
    float s = sc[l];
    float xv[4] = {x.x * s, x.y * s, x.z * s, x.w * s};
    #pragma unroll
    for (int j = 0; j < 4; ++j)
      Bp[l * S_BS + p + j] = __float2half_rn(xv[j]);
  }
  __syncthreads();

  const int wm = (wid >> 1) * 32, wn = (wid & 1) * 32;
  float acc[2][4][4];
  #pragma unroll
  for (int mi = 0; mi < 2; ++mi)
    #pragma unroll
    for (int nj = 0; nj < 4; ++nj)
      #pragma unroll
      for (int q = 0; q < 4; ++q) acc[mi][nj][q] = 0.0f;

  #pragma unroll
  for (int kk = 0; kk < 8; ++kk) {
    uint32_t ah4[2][4];
    #pragma unroll
    for (int mi = 0; mi < 2; ++mi) {
      uint32_t ad = sb + S_Ao
        + (uint32_t)(kk*16 + (lane & 7) + ((lane >> 4) << 3)) * (S_AS * 2)
        + (uint32_t)(wm + mi*16 + (lane & 8)) * 2;
      ldsm4t(ah4[mi], ad);
    }
    uint32_t bf[2][4];
    #pragma unroll
    for (int nj2 = 0; nj2 < 2; ++nj2) {
      uint32_t bd = sb + S_Bo
        + (uint32_t)(kk*16 + (lane & 15)) * (S_BS * 2)
        + (uint32_t)(wn + nj2*16 + ((lane >> 4) << 3)) * 2;
      ldsm4t(bf[nj2], bd);
    }
    #pragma unroll
    for (int nj2 = 0; nj2 < 2; ++nj2)
      #pragma unroll
      for (int mi = 0; mi < 2; ++mi)
        #pragma unroll
        for (int s2 = 0; s2 < 2; ++s2)
          mma16816h(acc[mi][nj2*2+s2], ah4[mi], bf[nj2][2*s2], bf[nj2][2*s2+1]);
  }

  const size_t ob = (((size_t)b * cNC + c) * cNH + h) * (cST * cHD);
  #pragma unroll
  for (int mi = 0; mi < 2; ++mi) {
    int row = wm + mi*16 + (lane >> 2);
    #pragma unroll
    for (int nj = 0; nj < 4; ++nj) {
      int col = wn + nj*8 + (lane & 3)*2;
      *(float2*)&g_cs[ob + (size_t)row * cHD + col] =
          make_float2(acc[mi][nj][0], acc[mi][nj][1]);
      *(float2*)&g_cs[ob + (size_t)(row + 8) * cHD + col] =
          make_float2(acc[mi][nj][2], acc[mi][nj][3]);
    }
  }
}

// ============= K5: inter-chunk carry scan (4-way state split) =============
__global__ void __launch_bounds__(256) k_carry()
{
  const int blk = blockIdx.x;            // cB*cNH*4
  const int bh = blk >> 2, qt = blk & 3;
  const int b = bh >> 6, h = bh & 63;
  const int off = qt * 2048;
  const int tid = threadIdx.x;
  float carry[8];
  #pragma unroll
  for (int j = 0; j < 8; ++j) carry[j] = 0.0f;
  for (int c = 0; c < cNC; ++c) {
    if (c > 0) {
      float eT = fexp(g_T[(size_t)bh * cNC + (c - 1)]);
      const size_t inb = (((size_t)b * cNC + (c - 1)) * cNH + h) * (cST * cHD) + off;
      #pragma unroll
      for (int j = 0; j < 8; ++j)
        carry[j] = carry[j] * eT + g_cs[inb + tid + j * 256];
    }
    const size_t ob = (((size_t)b * cNC + c) * cNH + h) * (cST * cHD) + off;
    #pragma unroll
    for (int j = 0; j < 8; ++j)
      g_pv[ob + tid + j * 256] = carry[j];
  }
}

// ============= K5.5: G = C * B^T per (b,c) via fp16 mma ===================
constexpr int G_AS = 136;
constexpr int G_Co = 0;
constexpr int G_Bo = 128 * G_AS * 2;            // 34816
constexpr int G_SMEM = 2 * 128 * G_AS * 2;      // 69632

__global__ void __launch_bounds__(256, 2) k_gmat()
{
  char* sm = dyn_smem;
  __half* Cp = (__half*)(sm + G_Co);   // [l][n]
  __half* Bp = (__half*)(sm + G_Bo);   // [s][n]
  const uint32_t sb = smem_to_u32(sm);
  const int c = blockIdx.x, b = blockIdx.y;
  const int tid = threadIdx.x, lane = tid & 31, wid = tid >> 5;
  const size_t rowbase = ((size_t)(b * cL + c * cCK)) * cCD;
  #pragma unroll 1
  for (int q = 0; q < 16; ++q) {
    int i = (tid + q * 256) * 4;
    int l = i >> 7, n = i & 127;
    float4 cv = *(const float4*)&g_xbc[rowbase + (size_t)l * cCD + cDS + cST + n];
    float4 bv = *(const float4*)&g_xbc[rowbase + (size_t)l * cCD + cDS + n];
    float cvv[4] = {cv.x, cv.y, cv.z, cv.w};
    float bvv[4] = {bv.x, bv.y, bv.z, bv.w};
    #pragma unroll
    for (int j = 0; j < 4; ++j) {
      Cp[l * G_AS + n + j] = __float2half_rn(cvv[j]);
      Bp[l * G_AS + n + j] = __float2half_rn(bvv[j]);
    }
  }
  __syncthreads();

  const int wm = (wid >> 1) * 32, wn = (wid & 1) * 64;
  float acc[2][8][4];
  #pragma unroll
  for (int mi = 0; mi < 2; ++mi)
    #pragma unroll
    for (int nj = 0; nj < 8; ++nj)
      #pragma unroll
      for (int q = 0; q < 4; ++q) acc[mi][nj][q] = 0.0f;

  #pragma unroll
  for (int kk = 0; kk < 8; ++kk) {
    uint32_t af[2][4];
    #pragma unroll
    for (int mi = 0; mi < 2; ++mi) {
      uint32_t ad = sb + G_Co
        + (uint32_t)(wm + mi*16 + (lane & 15)) * (G_AS * 2)
        + kk*32 + (lane >> 4) * 16;
      ldsm4(af[mi], ad);
    }
    #pragma unroll
    for (int nj2 = 0; nj2 < 4; ++nj2) {
      uint32_t bd = sb + G_Bo
        + (uint32_t)(wn + nj2*16 + (lane & 7) + ((lane >> 4) << 3)) * (G_AS * 2)
        + kk*32 + ((lane >> 3) & 1) * 16;
      uint32_t bf[4];
      ldsm4(bf, bd);
      #pragma unroll
      for (int mi = 0; mi < 2; ++mi)
        #pragma unroll
        for (int s = 0; s < 2; ++s)
          mma16816h(acc[mi][nj2*2+s], af[mi], bf[2*s], bf[2*s+1]);
    }
  }

  const size_t gb = ((size_t)(b * cNC + c)) * (cCK * cCK);
  #pragma unroll
  for (int mi = 0; mi < 2; ++mi) {
    int row = wm + mi*16 + (lane >> 2);
    #pragma unroll
    for (int nj = 0; nj < 8; ++nj) {
      int col = wn + nj*8 + (lane & 3)*2;
      __half a0 = __float2half_rn(acc[mi][nj][0]);
      __half a1 = __float2half_rn(acc[mi][nj][1]);
      __half a2 = __float2half_rn(acc[mi][nj][2]);
      __half a3 = __float2half_rn(acc[mi][nj][3]);
      unsigned short* p0 = &g_gmh[gb + (size_t)row * cCK + col];
      unsigned short* p1 = &g_gmh[gb + (size_t)(row + 8) * cCK + col];
      p0[0] = *(unsigned short*)&a0; p0[1] = *(unsigned short*)&a1;
      p1[0] = *(unsigned short*)&a2; p1[1] = *(unsigned short*)&a3;
    }
  }
}

// ============= K6: SSD Y kernel (fp16 mma single-B, 2 passes) =============
constexpr int Y_AS = 136;
constexpr int Y_BS = 72;
constexpr int Y_Ao  = 0;
constexpr int Y_Bo  = 128 * Y_AS * 2;          // 34816
constexpr int Y_ACS = Y_Bo + 128 * Y_BS * 2;   // 53248
constexpr int Y_DTS = Y_ACS + 512;             // 53760
constexpr int Y_SMEM = Y_DTS + 512;            // 54272

__global__ void __launch_bounds__(256, 2) k_ssd_y(const float* __restrict__ Dv)
{
  char* sm = dyn_smem;
  __half* Ap = (__half*)(sm + Y_Ao);
  __half* Bp = (__half*)(sm + Y_Bo);
  float* acs = (float*)(sm + Y_ACS);
  float* dts = (float*)(sm + Y_DTS);
  const uint32_t sb = smem_to_u32(sm);
  const int h = blockIdx.x, c = blockIdx.y, b = blockIdx.z;
  const int tid = threadIdx.x, lane = tid & 31, wid = tid >> 5;
  const size_t rowbase = ((size_t)(b * cL + c * cCK)) * cCD;
  const size_t acb = ((size_t)b * cNH + h) * cL + c * cCK;
  if (tid < 128) { acs[tid] = g_ac[acb + tid]; dts[tid] = g_dt[acb + tid]; }
  __syncthreads();

  const size_t gb = ((size_t)(b * cNC + c)) * (cCK * cCK);
  #pragma unroll 1
  for (int q = 0; q < 16; ++q) {
    int i = (tid + q * 256) * 4;
    int l = i >> 7, s = i & 127;
    ushort4 gv4 = *(const ushort4*)&g_gmh[gb + i];
    float gv[4];
    gv[0] = __half2float(*(__half*)&gv4.x);
    gv[1] = __half2float(*(__half*)&gv4.y);
    gv[2] = __half2float(*(__half*)&gv4.z);
    gv[3] = __half2float(*(__half*)&gv4.w);
    float al = acs[l];
    #pragma unroll
    for (int j = 0; j < 4; ++j) {
      int ss = s + j;
      float m = (ss <= l) ? fexp(al - acs[ss]) : 0.0f;
      Ap[l * Y_AS + ss] = __float2half_rn(gv[j] * m);
    }
  }
  #pragma unroll 1
  for (int q = 0; q < 8; ++q) {
    int i = (tid + q * 256) * 4;
    int s = i >> 6, p = i & 63;
    float4 x = *(const float4*)&g_xbc[rowbase + (size_t)s * cCD + h * cHD + p];
    float dv = dts[s];
    float xv[4] = {x.x * dv, x.y * dv, x.z * dv, x.w * dv};
    #pragma unroll
    for (int j = 0; j < 4; ++j)
      Bp[s * Y_BS + p + j] = __float2half_rn(xv[j]);
  }
  __syncthreads();

  const int wm = (wid >> 1) * 32, wn = (wid & 1) * 32;
  float acc[2][4][4];
  #pragma unroll
  for (int mi = 0; mi < 2; ++mi)
    #pragma unroll
    for (int nj = 0; nj < 4; ++nj)
      #pragma unroll
      for (int q = 0; q < 4; ++q) acc[mi][nj][q] = 0.0f;

  auto mma_pass = [&]() {
    #pragma unroll
    for (int kk = 0; kk < 8; ++kk) {
      uint32_t ah4[2][4];
      #pragma unroll
      for (int mi = 0; mi < 2; ++mi) {
        uint32_t ad = sb + Y_Ao
          + (uint32_t)(wm + mi*16 + (lane & 15)) * (Y_AS * 2)
          + kk*32 + (lane >> 4) * 16;
        ldsm4(ah4[mi], ad);
      }
      uint32_t bf[2][4];
      #pragma unroll
      for (int nj2 = 0; nj2 < 2; ++nj2) {
        uint32_t bd = sb + Y_Bo
          + (uint32_t)(kk*16 + (lane & 15)) * (Y_BS * 2)
          + (uint32_t)(wn + nj2*16 + ((lane >> 4) << 3)) * 2;
        ldsm4t(bf[nj2], bd);
      }
      #pragma unroll
      for (int nj2 = 0; nj2 < 2; ++nj2)
        #pragma unroll
        for (int mi = 0; mi < 2; ++mi)
          #pragma unroll
          for (int s2 = 0; s2 < 2; ++s2)
            mma16816h(acc[mi][nj2*2+s2], ah4[mi], bf[nj2][2*s2], bf[nj2][2*s2+1]);
    }
  };
  mma_pass();          // Y += Gm @ X'
  __syncthreads();

  #pragma unroll 1
  for (int q = 0; q < 16; ++q) {
    int i = (tid + q * 256) * 4;
    int l = i >> 7, n = i & 127;
    float4 cv = *(const float4*)&g_xbc[rowbase + (size_t)l * cCD + cDS + cST + n];
    float e = fexp(acs[l]);
    float cvv[4] = {cv.x * e, cv.y * e, cv.z * e, cv.w * e};
    #pragma unroll
    for (int j = 0; j < 4; ++j)
      Ap[l * Y_AS + n + j] = __float2half_rn(cvv[j]);
  }
  {
    const size_t pb = (((size_t)b * cNC + c) * cNH + h) * (cST * cHD);
    #pragma unroll 1
    for (int q = 0; q < 8; ++q) {
      int i = (tid + q * 256) * 4;
      int n = i >> 6, p = i & 63;
      float4 pv = *(const float4*)&g_pv[pb + i];
      float pvv[4] = {pv.x, pv.y, pv.z, pv.w};
      #pragma unroll
      for (int j = 0; j < 4; ++j)
        Bp[n * Y_BS + p + j] = __float2half_rn(pvv[j]);
    }
  }
  __syncthreads();
  mma_pass();          // Y += Ce @ P

  const float Dh = Dv[h];
  #pragma unroll
  for (int mi = 0; mi < 2; ++mi) {
    int row = wm + mi*16 + (lane >> 2);
    #pragma unroll
    for (int nj = 0; nj < 4; ++nj) {
      int col = wn + nj*8 + (lane & 3)*2;
      float2 x0 = *(const float2*)&g_xbc[rowbase + (size_t)row * cCD + h * cHD + col];
      float2 x1 = *(const float2*)&g_xbc[rowbase + (size_t)(row+8) * cCD + h * cHD + col];
      size_t y0 = ((size_t)(b * cL + c * cCK + row)) * cDS + h * cHD + col;
      size_t y1 = ((size_t)(b * cL + c * cCK + row + 8)) * cDS + h * cHD + col;
      *(float2*)&g_y[y0] = make_float2(acc[mi][nj][0] + Dh * x0.x,
                                       acc[mi][nj][1] + Dh * x0.y);
      *(float2*)&g_y[y1] = make_float2(acc[mi][nj][2] + Dh * x1.x,
                                       acc[mi][nj][3] + Dh * x1.y);
    }
  }
}

// ============= K7: gate (silu(z)) + RMSNorm + fp16 cvt (fused) ============
__global__ void __launch_bounds__(256) k_gate_norm(const float* __restrict__ norm_w)
{
  const int row = blockIdx.x;
  const int tid = threadIdx.x;
  const size_t zb = (size_t)row * cDP;
  const size_t yb = (size_t)row * cDS;
  float v[16];
  float ss = 0.0f;
  #pragma unroll
  for (int q = 0; q < 16; ++q) {
    int i = tid + q * 256;
    float z = g_zx[zb + i];
    float y = g_y[yb + i];
    float t = y * z * fsig(z);
    v[q] = t;
    ss += t * t;
  }
  #pragma unroll
  for (int o = 16; o > 0; o >>= 1) ss += __shfl_xor_sync(0xffffffffu, ss, o);
  __shared__ float red[8];
  if ((tid & 31) == 0) red[tid >> 5] = ss;
  __syncthreads();
  float tot = 0.0f;
  #pragma unroll
  for (int j = 0; j < 8; ++j) tot += red[j];
  const float scale = rsqrtf(tot / (float)cDS + cEPS);
  #pragma unroll
  for (int q = 0; q < 16; ++q) {
    int i = tid + q * 256;
    float t = v[q] * scale * norm_w[i];
    __half hh = __float2half_rn(t);
    g_ah[yb + i] = *(unsigned short*)&hh;
  }
}

// ============= K9: out + reverse(out) =====================================
__global__ void __launch_bounds__(256) k_revadd(float* __restrict__ out)
{
  const int idx4 = blockIdx.x * 256 + threadIdx.x;
  const int tot4 = cB * cL * cDM / 4;
  if (idx4 >= tot4) return;
  const int i = idx4 * 4;
  const int b = i / (cL * cDM);
  const int r = i - b * (cL * cDM);
  const int l = r / cDM;
  const int d = r - l * cDM;
  const size_t rev = ((size_t)b * cL + (cL - 1 - l)) * cDM + d;
  float4 a = *(const float4*)(&g_o[i]);
  float4 c = *(const float4*)(&g_o[rev]);
  a.x += c.x; a.y += c.y; a.z += c.z; a.w += c.w;
  *(float4*)(out + i) = a;
}

// ==========================================================================
extern "C" void kernel_launch(void* const* d_in, const int* in_sizes, int n_in,
                              void* d_out, int out_size) {
  const float* u       = (const float*)d_in[0];
  const float* W_in    = (const float*)d_in[1];
  const float* conv_w  = (const float*)d_in[2];
  const float* conv_b  = (const float*)d_in[3];
  const float* dt_bias = (const float*)d_in[4];
  const float* A_log   = (const float*)d_in[5];
  const float* Dv      = (const float*)d_in[6];
  const float* norm_w  = (const float*)d_in[7];
  const float* W_out   = (const float*)d_in[8];
  float* out = (float*)d_out;

  float* zx; cudaGetSymbolAddress((void**)&zx, g_zx);
  float* ob; cudaGetSymbolAddress((void**)&ob, g_o);
  unsigned short *ah, *bh, *b2h;
  cudaGetSymbolAddress((void**)&ah,  g_ah);
  cudaGetSymbolAddress((void**)&bh,  g_bh);
  cudaGetSymbolAddress((void**)&b2h, g_b2h);

  cudaFuncSetAttribute(gemm_mma, cudaFuncAttributeMaxDynamicSharedMemorySize,
                       SMEM_GEMM);
  cudaFuncSetAttribute(k_gmat, cudaFuncAttributeMaxDynamicSharedMemorySize,
                       G_SMEM);
  cudaFuncSetAttribute(k_states, cudaFuncAttributeMaxDynamicSharedMemorySize,
                       S_SMEM);
  cudaFuncSetAttribute(k_ssd_y, cudaFuncAttributeMaxDynamicSharedMemorySize,
                       Y_SMEM);

  const int M = cB * cL;   // 4096

  // --- prep: u -> fp16; W_in (padded), W_out -> fp16 ---
  {
    long totA = (long)M * cDM;
    k_cvt_h<<<(unsigned)((totA/4 + 255)/256), 256>>>(u, ah, totA);
    long totB = (long)cNPAD1 * cDM;
    k_cvt_h_pad<<<(unsigned)((totB/4 + 255)/256), 256>>>(W_in, bh, cDP, cDM, totB);
    long totB2 = (long)cDM * cDS;
    k_cvt_h<<<(unsigned)((totB2/4 + 255)/256), 256>>>(W_out, b2h, totB2);
  }
  // --- GEMM1: zx[4096, 8512] ---
  {
    dim3 grid(cNPAD1 / 128, M / 128);
    gemm_mma<<<grid, 256, SMEM_GEMM>>>(
        (const __half*)ah, (const __half*)bh, zx, M, cDP, cDM);
  }
  // --- conv + silu + dt ---
  k_conv<<<cB * cL / CTL, 256>>>(conv_w, conv_b, dt_bias);
  // --- chunk states (fp16 mma, fused scan) ---
  { dim3 grid(cNH, cNC, cB); k_states<<<grid, 256, S_SMEM>>>(A_log); }
  // --- carry scan (4-way split) ---
  k_carry<<<cB * cNH * 4, 256>>>();
  // --- G (fp16 mma) ---
  { dim3 grid(cNC, cB); k_gmat<<<grid, 256, G_SMEM>>>(); }
  // --- Y (fp16 mma) ---
  { dim3 grid(cNH, cNC, cB); k_ssd_y<<<grid, 256, Y_SMEM>>>(Dv); }
  // --- gate + rmsnorm + fp16 cvt (fused) ---
  k_gate_norm<<<cB * cL, 256>>>(norm_w);
  // --- GEMM2: o[4096, 2048] ---
  {
    dim3 grid(cDM / 128, M / 128);
    gemm_mma<<<grid, 256, SMEM_GEMM>>>(
        (const __half*)ah, (const __half*)b2h, ob, M, cDM, cDS);
  }
  // --- out + reverse(out) ---
  k_revadd<<<(cB * cL * cDM / 4 + 255) / 256, 256>>>(out);
}

// round 17
// speedup vs baseline: 1.6256x; 1.0083x over previous
#include <cuda_runtime.h>
#include <cuda_bf16.h>
#include <cuda_fp16.h>
#include <cstdint>

#define DEVFN static __device__ __forceinline__

constexpr int cB  = 2;
constexpr int cL  = 2048;
constexpr int cDM = 2048;
constexpr int cDS = 4096;
constexpr int cST = 128;
constexpr int cNH = 64;
constexpr int cHD = 64;
constexpr int cCK = 128;
constexpr int cNC = cL / cCK;        // 16
constexpr int cDP = 2*cDS + 2*cST + cNH;   // 8512
constexpr int cCD = cDS + 2*cST;           // 4352
constexpr float cEPS = 1e-5f;

constexpr int cNPAD1 = 8576;         // padded N for GEMM1 (67 * 128)

// ---------------- scratch ----------
__device__ float g_zx [(size_t)cB*cL*cDP];
__device__ float g_xbc[(size_t)cB*cL*cCD];
__device__ float g_dt [(size_t)cB*cNH*cL];
__device__ float g_ac [(size_t)cB*cNH*cL];
__device__ float g_T  [(size_t)cB*cNH*cNC];
__device__ float g_cs [(size_t)cB*cNC*cNH*cST*cHD];
__device__ float g_pv [(size_t)cB*cNC*cNH*cST*cHD];
__device__ unsigned short g_gmh[(size_t)cB*cNC*cCK*cCK];   // G in fp16
__device__ float g_y  [(size_t)cB*cL*cDS];
__device__ float g_o  [(size_t)cB*cL*cDM];
__device__ unsigned short g_ah [(size_t)4096*4096];
__device__ unsigned short g_bh [(size_t)cNPAD1*2048];
__device__ unsigned short g_b2h[(size_t)cDM*cDS];

// ---------------- math helpers --------------------------------------------
DEVFN float fexp(float x) {
  float t = x * 1.44269504088896340736f;
  t = fminf(fmaxf(t, -126.0f), 126.0f);
  float fi = rintf(t);
  float f  = t - fi;
  float p = 1.5403530393381610e-4f;
  p = fmaf(p, f, 1.3333558146428443e-3f);
  p = fmaf(p, f, 9.6181291076284772e-3f);
  p = fmaf(p, f, 5.5504108664821580e-2f);
  p = fmaf(p, f, 2.4022650695910071e-1f);
  p = fmaf(p, f, 6.9314718055994531e-1f);
  p = fmaf(p, f, 1.0f);
  int i = (int)fi;
  return __int_as_float((i + 127) << 23) * p;
}
DEVFN float fsig(float x) { return 1.0f / (1.0f + fexp(-x)); }

DEVFN uint32_t smem_to_u32(const void* p) {
  uint32_t a;
  asm("{ .reg .u64 t; cvta.to.shared.u64 t, %1; cvt.u32.u64 %0, t; }"
      : "=r"(a) : "l"(p));
  return a;
}
DEVFN void cp16(uint32_t saddr, const void* gptr) {
  asm volatile("cp.async.cg.shared.global [%0], [%1], 16;"
               :: "r"(saddr), "l"(gptr) : "memory");
}
DEVFN void ldsm4(uint32_t (&r)[4], uint32_t a) {
  asm volatile("ldmatrix.sync.aligned.m8n8.x4.shared.b16 {%0,%1,%2,%3}, [%4];"
    : "=r"(r[0]), "=r"(r[1]), "=r"(r[2]), "=r"(r[3]) : "r"(a));
}
DEVFN void ldsm4t(uint32_t (&r)[4], uint32_t a) {
  asm volatile("ldmatrix.sync.aligned.m8n8.x4.trans.shared.b16 {%0,%1,%2,%3}, [%4];"
    : "=r"(r[0]), "=r"(r[1]), "=r"(r[2]), "=r"(r[3]) : "r"(a));
}
DEVFN void mma16816h(float (&d)[4], const uint32_t (&a)[4], uint32_t b0, uint32_t b1) {
  asm volatile("mma.sync.aligned.m16n8k16.row.col.f32.f16.f16.f32 "
    "{%0,%1,%2,%3},{%4,%5,%6,%7},{%8,%9},{%0,%1,%2,%3};"
    : "+f"(d[0]), "+f"(d[1]), "+f"(d[2]), "+f"(d[3])
    : "r"(a[0]), "r"(a[1]), "r"(a[2]), "r"(a[3]), "r"(b0), "r"(b1));
}

extern __shared__ char dyn_smem[];

// ============= K0: fused fp32 -> fp16 conversion for u, W_in(pad), W_out ===
constexpr long CV_NA  = (long)cB*cL*cDM / 4;          // 2,097,152 float4
constexpr long CV_NB  = (long)cNPAD1*cDM / 4;         // 4,390,912
constexpr long CV_NB2 = (long)cDM*cDS / 4;            // 2,097,152
constexpr long CV_TOT = CV_NA + CV_NB + CV_NB2;

__global__ void __launch_bounds__(256) k_cvt_all(
    const float* __restrict__ u, const float* __restrict__ W_in,
    const float* __restrict__ W_out,
    unsigned short* __restrict__ ah, unsigned short* __restrict__ bh,
    unsigned short* __restrict__ b2h)
{
  long t = (long)blockIdx.x * 256 + threadIdx.x;
  if (t >= CV_TOT) return;
  const float* src;
  unsigned short* dst;
  long i4;
  bool pad = false;
  if (t < CV_NA) {
    src = u; dst = ah; i4 = t;
  } else if (t < CV_NA + CV_NB) {
    i4 = t - CV_NA; src = W_in; dst = bh;
    pad = (i4 * 4) >= (long)cDP * cDM;      // rows >= cDP zero-padded
  } else {
    i4 = t - CV_NA - CV_NB; src = W_out; dst = b2h;
  }
  long i = i4 * 4;
  float4 v = pad ? make_float4(0.f,0.f,0.f,0.f) : *(const float4*)(src + i);
  __half h0 = __float2half_rn(v.x), h1 = __float2half_rn(v.y);
  __half h2 = __float2half_rn(v.z), h3 = __float2half_rn(v.w);
  ushort4 hv;
  hv.x = *(unsigned short*)&h0; hv.y = *(unsigned short*)&h1;
  hv.z = *(unsigned short*)&h2; hv.w = *(unsigned short*)&h3;
  *(ushort4*)(dst + i) = hv;
}

// ============= fp16 1-MMA GEMM: C[M,N] = A[M,K] * B[N,K]^T ================
constexpr int ROWB  = 80;
constexpr int TILEB = 128 * ROWB;         // 10240
constexpr int STGB  = 2 * TILEB;
constexpr int SMEM_GEMM = 3 * STGB;       // 61440

__global__ void __launch_bounds__(256, 2) gemm_mma(
    const __half* __restrict__ A, const __half* __restrict__ B,
    float* __restrict__ C, int M, int N, int K)
{
  char* smem = dyn_smem;
  const uint32_t sb0 = smem_to_u32(smem);
  const int tid = threadIdx.x;
  const int lane = tid & 31, wid = tid >> 5;
  const int bm = blockIdx.y * 128, bn = blockIdx.x * 128;
  const int wm = (wid >> 1) * 32, wn = (wid & 1) * 64;

  float acc[2][8][4];
  #pragma unroll
  for (int i = 0; i < 2; ++i)
    #pragma unroll
    for (int j = 0; j < 8; ++j)
      #pragma unroll
      for (int q = 0; q < 4; ++q) acc[i][j][q] = 0.0f;

  auto load_tile = [&](int kt, int stg) {
    const uint32_t sb = sb0 + stg * STGB;
    const long kb = (long)kt * 32;
    #pragma unroll
    for (int i = 0; i < 2; ++i) {
      int o = tid + 256 * i;
      int row = o >> 2, seg = o & 3;
      uint32_t soff = row * ROWB + seg * 16;
      cp16(sb + soff,         A + (long)(bm + row) * K + kb + seg * 8);
      cp16(sb + TILEB + soff, B + (long)(bn + row) * K + kb + seg * 8);
    }
    asm volatile("cp.async.commit_group;" ::: "memory");
  };

  const int KT = K >> 5;
  load_tile(0, 0);
  load_tile(1, 1);
  for (int kt = 0; kt < KT; ++kt) {
    const int stg = kt % 3;
    if (kt < KT - 1) {
      asm volatile("cp.async.wait_group 1;" ::: "memory");
    } else {
      asm volatile("cp.async.wait_group 0;" ::: "memory");
    }
    __syncthreads();
    if (kt + 2 < KT) load_tile(kt + 2, (kt + 2) % 3);
    const uint32_t sb = sb0 + stg * STGB;
    #pragma unroll
    for (int h = 0; h < 2; ++h) {
      uint32_t ah[2][4];
      #pragma unroll
      for (int mi = 0; mi < 2; ++mi) {
        uint32_t ad = sb + (uint32_t)(wm + mi*16 + (lane & 15)) * ROWB
                         + h*32 + (lane >> 4) * 16;
        ldsm4(ah[mi], ad);
      }
      #pragma unroll
      for (int nj2 = 0; nj2 < 4; ++nj2) {
        uint32_t bd = sb + TILEB
          + (uint32_t)(wn + nj2*16 + (lane & 7) + ((lane >> 4) << 3)) * ROWB
          + h*32 + ((lane >> 3) & 1) * 16;
        uint32_t bf[4];
        ldsm4(bf, bd);
        #pragma unroll
        for (int mi = 0; mi < 2; ++mi)
          #pragma unroll
          for (int s = 0; s < 2; ++s)
            mma16816h(acc[mi][nj2*2+s], ah[mi], bf[2*s], bf[2*s+1]);
      }
    }
  }

  #pragma unroll
  for (int mi = 0; mi < 2; ++mi) {
    int row = bm + wm + mi*16 + (lane >> 2);
    #pragma unroll
    for (int nj = 0; nj < 8; ++nj) {
      int col = bn + wn + nj*8 + (lane & 3)*2;
      if (col < N) {
        *(float2*)(C + (long)row * N + col) =
            make_float2(acc[mi][nj][0], acc[mi][nj][1]);
        *(float2*)(C + (long)(row + 8) * N + col) =
            make_float2(acc[mi][nj][2], acc[mi][nj][3]);
      }
    }
  }
}

// ============= K2: conv1d + SiLU + softplus(dt), 8 rows per block =========
constexpr int CTL = 8;
__global__ void __launch_bounds__(256) k_conv(
    const float* __restrict__ conv_w, const float* __restrict__ conv_b,
    const float* __restrict__ dt_bias)
{
  const int blk = blockIdx.x;
  const int b = blk / (cL / CTL), lt = blk % (cL / CTL);
  const int l0 = lt * CTL;
  const int tid = threadIdx.x;
  const size_t rb = ((size_t)(b * cL + l0)) * cDP + cDS;
  const size_t ob = ((size_t)(b * cL + l0)) * cCD;
  #pragma unroll 1
  for (int q = 0; q < 5; ++q) {
    int c4 = tid + q * 256;
    if (c4 >= cCD / 4) break;
    int c = c4 * 4;
    float4 wa = *(const float4*)(conv_w + c*3);
    float4 wb = *(const float4*)(conv_w + c*3 + 4);
    float4 wc = *(const float4*)(conv_w + c*3 + 8);
    float4 bs = *(const float4*)(conv_b + c);
    float4 xr[CTL + 2];
    #pragma unroll
    for (int r = 0; r < CTL + 2; ++r) {
      int gl = l0 - 2 + r;
      xr[r] = (gl >= 0) ? *(const float4*)(&g_zx[rb + (size_t)(r - 2) * cDP + c])
                        : make_float4(0.f, 0.f, 0.f, 0.f);
    }
    #pragma unroll
    for (int t = 0; t < CTL; ++t) {
      float4 x2 = xr[t], x1 = xr[t + 1], x0 = xr[t + 2];
      float4 s;
      s.x = bs.x + x2.x*wa.x + x1.x*wa.y + x0.x*wa.z;
      s.y = bs.y + x2.y*wa.w + x1.y*wb.x + x0.y*wb.y;
      s.z = bs.z + x2.z*wb.z + x1.z*wb.w + x0.z*wc.x;
      s.w = bs.w + x2.w*wc.y + x1.w*wc.z + x0.w*wc.w;
      s.x *= fsig(s.x); s.y *= fsig(s.y); s.z *= fsig(s.z); s.w *= fsig(s.w);
      *(float4*)(&g_xbc[ob + (size_t)t * cCD + c]) = s;
    }
  }
  #pragma unroll
  for (int i = 0; i < 2; ++i) {
    int idx = tid + i * 256;
    int hh = idx & 63, t = idx >> 6;
    float v = g_zx[((size_t)(b * cL + l0 + t)) * cDP + (cDP - cNH) + hh]
              + dt_bias[hh];
    float sp = (v > 15.0f) ? v : log1pf(expf(v));
    g_dt[((size_t)b * cNH + hh) * cL + l0 + t] = sp;
  }
}

// ============= K4: chunk states (fp16 mma, fused per-chunk scan) ==========
constexpr int S_AS  = 136;
constexpr int S_BS  = 72;
constexpr int S_Ao  = 0;
constexpr int S_Bo  = 128 * S_AS * 2;          // 34816
constexpr int S_SCo = S_Bo + 128 * S_BS * 2;   // 53248
constexpr int S_ACo = S_SCo + 512;             // 53760
constexpr int S_SMEM = S_ACo + 512;            // 54272

__global__ void __launch_bounds__(256, 2) k_states(const float* __restrict__ A_log)
{
  char* sm = dyn_smem;
  __half* Ap = (__half*)(sm + S_Ao);
  __half* Bp = (__half*)(sm + S_Bo);
  float* sc = (float*)(sm + S_SCo);
  float* sA = (float*)(sm + S_ACo);
  const uint32_t sb = smem_to_u32(sm);
  const int h = blockIdx.x, c = blockIdx.y, b = blockIdx.z;
  const int tid = threadIdx.x, lane = tid & 31, wid = tid >> 5;
  const size_t rowbase = ((size_t)(b * cL + c * cCK)) * cCD;
  const size_t acb = ((size_t)b * cNH + h) * cL + c * cCK;

  const float ahv = -expf(A_log[h]);
  if (tid < 128) sA[tid] = g_dt[acb + tid] * ahv;
  __syncthreads();
  #pragma unroll
  for (int off = 1; off < 128; off <<= 1) {
    float t = 0.0f;
    if (tid < 128 && tid >= off) t = sA[tid - off];
    __syncthreads();
    if (tid < 128) sA[tid] += t;
    __syncthreads();
  }
  if (tid < 128) {
    float T = sA[127];
    g_ac[acb + tid] = sA[tid];
    if (tid == 127) g_T[((size_t)b * cNH + h) * cNC + c] = T;
    sc[tid] = g_dt[acb + tid] * fexp(T - sA[tid]);
  }
  __syncthreads();

  #pragma unroll 1
  for (int q = 0; q < 16; ++q) {
    int i = (tid + q * 256) * 4;
    int l = i >> 7, n = i & 127;
    float4 v = *(const float4*)&g_xbc[rowbase + (size_t)l * cCD + cDS + n];
    float vv[4] = {v.x, v.y, v.z, v.w};
    #pragma unroll
    for (int j = 0; j < 4; ++j)
      Ap[l * S_AS + n + j] = __float2half_rn(vv[j]);
  }
  #pragma unroll 1
  for (int q = 0; q < 8; ++q) {
    int i = (tid + q * 256) * 4;
    int l = i >> 6, p = i & 63;
    float4 x = *(const float4*)&g_xbc[rowbase + (size_t)l * cCD + h * cHD + p];
    float s = sc[l];
    float xv[4] = {x.x * s, x.y * s, x.z * s, x.w * s};
    #pragma unroll
    for (int j = 0; j < 4; ++j)
      Bp[l * S_BS + p + j] = __float2half_rn(xv[j]);
  }
  __syncthreads();

  const int wm = (wid >> 1) * 32, wn = (wid & 1) * 32;
  float acc[2][4][4];
  #pragma unroll
  for (int mi = 0; mi < 2; ++mi)
    #pragma unroll
    for (int nj = 0; nj < 4; ++nj)
      #pragma unroll
      for (int q = 0; q < 4; ++q) acc[mi][nj][q] = 0.0f;

  #pragma unroll
  for (int kk = 0; kk < 8; ++kk) {
    uint32_t ah4[2][4];
    #pragma unroll
    for (int mi = 0; mi < 2; ++mi) {
      uint32_t ad = sb + S_Ao
        + (uint32_t)(kk*16 + (lane & 7) + ((lane >> 4) << 3)) * (S_AS * 2)
        + (uint32_t)(wm + mi*16 + (lane & 8)) * 2;
      ldsm4t(ah4[mi], ad);
    }
    uint32_t bf[2][4];
    #pragma unroll
    for (int nj2 = 0; nj2 < 2; ++nj2) {
      uint32_t bd = sb + S_Bo
        + (uint32_t)(kk*16 + (lane & 15)) * (S_BS * 2)
        + (uint32_t)(wn + nj2*16 + ((lane >> 4) << 3)) * 2;
      ldsm4t(bf[nj2], bd);
    }
    #pragma unroll
    for (int nj2 = 0; nj2 < 2; ++nj2)
      #pragma unroll
      for (int mi = 0; mi < 2; ++mi)
        #pragma unroll
        for (int s2 = 0; s2 < 2; ++s2)
          mma16816h(acc[mi][nj2*2+s2], ah4[mi], bf[nj2][2*s2], bf[nj2][2*s2+1]);
  }

  const size_t ob = (((size_t)b * cNC + c) * cNH + h) * (cST * cHD);
  #pragma unroll
  for (int mi = 0; mi < 2; ++mi) {
    int row = wm + mi*16 + (lane >> 2);
    #pragma unroll
    for (int nj = 0; nj < 4; ++nj) {
      int col = wn + nj*8 + (lane & 3)*2;
      *(float2*)&g_cs[ob + (size_t)row * cHD + col] =
          make_float2(acc[mi][nj][0], acc[mi][nj][1]);
      *(float2*)&g_cs[ob + (size_t)(row + 8) * cHD + col] =
          make_float2(acc[mi][nj][2], acc[mi][nj][3]);
    }
  }
}

// ============= K5: inter-chunk carry scan (4-way state split) =============
__global__ void __launch_bounds__(256) k_carry()
{
  const int blk = blockIdx.x;            // cB*cNH*4
  const int bh = blk >> 2, qt = blk & 3;
  const int b = bh >> 6, h = bh & 63;
  const int off = qt * 2048;
  const int tid = threadIdx.x;
  float carry[8];
  #pragma unroll
  for (int j = 0; j < 8; ++j) carry[j] = 0.0f;
  for (int c = 0; c < cNC; ++c) {
    if (c > 0) {
      float eT = fexp(g_T[(size_t)bh * cNC + (c - 1)]);
      const size_t inb = (((size_t)b * cNC + (c - 1)) * cNH + h) * (cST * cHD) + off;
      #pragma unroll
      for (int j = 0; j < 8; ++j)
        carry[j] = carry[j] * eT + g_cs[inb + tid + j * 256];
    }
    const size_t ob = (((size_t)b * cNC + c) * cNH + h) * (cST * cHD) + off;
    #pragma unroll
    for (int j = 0; j < 8; ++j)
      g_pv[ob + tid + j * 256] = carry[j];
  }
}

// ============= K5.5: G = C * B^T per (b,c) via fp16 mma ===================
constexpr int G_AS = 136;
constexpr int G_Co = 0;
constexpr int G_Bo = 128 * G_AS * 2;            // 34816
constexpr int G_SMEM = 2 * 128 * G_AS * 2;      // 69632

__global__ void __launch_bounds__(256, 2) k_gmat()
{
  char* sm = dyn_smem;
  __half* Cp = (__half*)(sm + G_Co);   // [l][n]
  __half* Bp = (__half*)(sm + G_Bo);   // [s][n]
  const uint32_t sb = smem_to_u32(sm);
  const int c = blockIdx.x, b = blockIdx.y;
  const int tid = threadIdx.x, lane = tid & 31, wid = tid >> 5;
  const size_t rowbase = ((size_t)(b * cL + c * cCK)) * cCD;
  #pragma unroll 1
  for (int q = 0; q < 16; ++q) {
    int i = (tid + q * 256) * 4;
    int l = i >> 7, n = i & 127;
    float4 cv = *(const float4*)&g_xbc[rowbase + (size_t)l * cCD + cDS + cST + n];
    float4 bv = *(const float4*)&g_xbc[rowbase + (size_t)l * cCD + cDS + n];
    float cvv[4] = {cv.x, cv.y, cv.z, cv.w};
    float bvv[4] = {bv.x, bv.y, bv.z, bv.w};
    #pragma unroll
    for (int j = 0; j < 4; ++j) {
      Cp[l * G_AS + n + j] = __float2half_rn(cvv[j]);
      Bp[l * G_AS + n + j] = __float2half_rn(bvv[j]);
    }
  }
  __syncthreads();

  const int wm = (wid >> 1) * 32, wn = (wid & 1) * 64;
  float acc[2][8][4];
  #pragma unroll
  for (int mi = 0; mi < 2; ++mi)
    #pragma unroll
    for (int nj = 0; nj < 8; ++nj)
      #pragma unroll
      for (int q = 0; q < 4; ++q) acc[mi][nj][q] = 0.0f;

  #pragma unroll
  for (int kk = 0; kk < 8; ++kk) {
    uint32_t af[2][4];
    #pragma unroll
    for (int mi = 0; mi < 2; ++mi) {
      uint32_t ad = sb + G_Co
        + (uint32_t)(wm + mi*16 + (lane & 15)) * (G_AS * 2)
        + kk*32 + (lane >> 4) * 16;
      ldsm4(af[mi], ad);
    }
    #pragma unroll
    for (int nj2 = 0; nj2 < 4; ++nj2) {
      uint32_t bd = sb + G_Bo
        + (uint32_t)(wn + nj2*16 + (lane & 7) + ((lane >> 4) << 3)) * (G_AS * 2)
        + kk*32 + ((lane >> 3) & 1) * 16;
      uint32_t bf[4];
      ldsm4(bf, bd);
      #pragma unroll
      for (int mi = 0; mi < 2; ++mi)
        #pragma unroll
        for (int s = 0; s < 2; ++s)
          mma16816h(acc[mi][nj2*2+s], af[mi], bf[2*s], bf[2*s+1]);
    }
  }

  const size_t gb = ((size_t)(b * cNC + c)) * (cCK * cCK);
  #pragma unroll
  for (int mi = 0; mi < 2; ++mi) {
    int row = wm + mi*16 + (lane >> 2);
    #pragma unroll
    for (int nj = 0; nj < 8; ++nj) {
      int col = wn + nj*8 + (lane & 3)*2;
      __half a0 = __float2half_rn(acc[mi][nj][0]);
      __half a1 = __float2half_rn(acc[mi][nj][1]);
      __half a2 = __float2half_rn(acc[mi][nj][2]);
      __half a3 = __float2half_rn(acc[mi][nj][3]);
      unsigned short* p0 = &g_gmh[gb + (size_t)row * cCK + col];
      unsigned short* p1 = &g_gmh[gb + (size_t)(row + 8) * cCK + col];
      p0[0] = *(unsigned short*)&a0; p0[1] = *(unsigned short*)&a1;
      p1[0] = *(unsigned short*)&a2; p1[1] = *(unsigned short*)&a3;
    }
  }
}

// ============= K6: SSD Y kernel (single-stage: both passes staged once) ===
constexpr int Y_AS = 136;
constexpr int Y_BS = 72;
constexpr int Y_A1  = 0;
constexpr int Y_A2  = 128 * Y_AS * 2;            // 34816
constexpr int Y_B1  = 2 * 128 * Y_AS * 2;        // 69632
constexpr int Y_B2  = Y_B1 + 128 * Y_BS * 2;     // 88064
constexpr int Y_ACS = Y_B2 + 128 * Y_BS * 2;     // 106496
constexpr int Y_DTS = Y_ACS + 512;               // 107008
constexpr int Y_SMEM = Y_DTS + 512;              // 107520

__global__ void __launch_bounds__(256, 2) k_ssd_y(const float* __restrict__ Dv)
{
  char* sm = dyn_smem;
  __half* A1 = (__half*)(sm + Y_A1);
  __half* A2 = (__half*)(sm + Y_A2);
  __half* B1 = (__half*)(sm + Y_B1);
  __half* B2 = (__half*)(sm + Y_B2);
  float* acs = (float*)(sm + Y_ACS);
  float* dts = (float*)(sm + Y_DTS);
  const uint32_t sb = smem_to_u32(sm);
  const int h = blockIdx.x, c = blockIdx.y, b = blockIdx.z;
  const int tid = threadIdx.x, lane = tid & 31, wid = tid >> 5;
  const size_t rowbase = ((size_t)(b * cL + c * cCK)) * cCD;
  const size_t acb = ((size_t)b * cNH + h) * cL + c * cCK;
  if (tid < 128) { acs[tid] = g_ac[acb + tid]; dts[tid] = g_dt[acb + tid]; }
  __syncthreads();

  // ---- stage ALL four operands, then one mma sequence ----
  const size_t gb = ((size_t)(b * cNC + c)) * (cCK * cCK);
  #pragma unroll 1
  for (int q = 0; q < 16; ++q) {           // A1 = Gm (masked, decayed)
    int i = (tid + q * 256) * 4;
    int l = i >> 7, s = i & 127;
    ushort4 gv4 = *(const ushort4*)&g_gmh[gb + i];
    float gv[4];
    gv[0] = __half2float(*(__half*)&gv4.x);
    gv[1] = __half2float(*(__half*)&gv4.y);
    gv[2] = __half2float(*(__half*)&gv4.z);
    gv[3] = __half2float(*(__half*)&gv4.w);
    float al = acs[l];
    #pragma unroll
    for (int j = 0; j < 4; ++j) {
      int ss = s + j;
      float m = (ss <= l) ? fexp(al - acs[ss]) : 0.0f;
      A1[l * Y_AS + ss] = __float2half_rn(gv[j] * m);
    }
  }
  #pragma unroll 1
  for (int q = 0; q < 16; ++q) {           // A2 = C * exp(ac_l)
    int i = (tid + q * 256) * 4;
    int l = i >> 7, n = i & 127;
    float4 cv = *(const float4*)&g_xbc[rowbase + (size_t)l * cCD + cDS + cST + n];
    float e = fexp(acs[l]);
    float cvv[4] = {cv.x * e, cv.y * e, cv.z * e, cv.w * e};
    #pragma unroll
    for (int j = 0; j < 4; ++j)
      A2[l * Y_AS + n + j] = __float2half_rn(cvv[j]);
  }
  #pragma unroll 1
  for (int q = 0; q < 8; ++q) {            // B1 = x * dt
    int i = (tid + q * 256) * 4;
    int s = i >> 6, p = i & 63;
    float4 x = *(const float4*)&g_xbc[rowbase + (size_t)s * cCD + h * cHD + p];
    float dv = dts[s];
    float xv[4] = {x.x * dv, x.y * dv, x.z * dv, x.w * dv};
    #pragma unroll
    for (int j = 0; j < 4; ++j)
      B1[s * Y_BS + p + j] = __float2half_rn(xv[j]);
  }
  {
    const size_t pb = (((size_t)b * cNC + c) * cNH + h) * (cST * cHD);
    #pragma unroll 1
    for (int q = 0; q < 8; ++q) {          // B2 = prev states
      int i = (tid + q * 256) * 4;
      int n = i >> 6, p = i & 63;
      float4 pv = *(const float4*)&g_pv[pb + i];
      float pvv[4] = {pv.x, pv.y, pv.z, pv.w};
      #pragma unroll
      for (int j = 0; j < 4; ++j)
        B2[n * Y_BS + p + j] = __float2half_rn(pvv[j]);
    }
  }
  __syncthreads();

  const int wm = (wid >> 1) * 32, wn = (wid & 1) * 32;
  float acc[2][4][4];
  #pragma unroll
  for (int mi = 0; mi < 2; ++mi)
    #pragma unroll
    for (int nj = 0; nj < 4; ++nj)
      #pragma unroll
      for (int q = 0; q < 4; ++q) acc[mi][nj][q] = 0.0f;

  #pragma unroll
  for (int pass = 0; pass < 2; ++pass) {
    const uint32_t aoff = (pass == 0) ? Y_A1 : Y_A2;
    const uint32_t boff = (pass == 0) ? Y_B1 : Y_B2;
    #pragma unroll
    for (int kk = 0; kk < 8; ++kk) {
      uint32_t ah4[2][4];
      #pragma unroll
      for (int mi = 0; mi < 2; ++mi) {
        uint32_t ad = sb + aoff
          + (uint32_t)(wm + mi*16 + (lane & 15)) * (Y_AS * 2)
          + kk*32 + (lane >> 4) * 16;
        ldsm4(ah4[mi], ad);
      }
      uint32_t bf[2][4];
      #pragma unroll
      for (int nj2 = 0; nj2 < 2; ++nj2) {
        uint32_t bd = sb + boff
          + (uint32_t)(kk*16 + (lane & 15)) * (Y_BS * 2)
          + (uint32_t)(wn + nj2*16 + ((lane >> 4) << 3)) * 2;
        ldsm4t(bf[nj2], bd);
      }
      #pragma unroll
      for (int nj2 = 0; nj2 < 2; ++nj2)
        #pragma unroll
        for (int mi = 0; mi < 2; ++mi)
          #pragma unroll
          for (int s2 = 0; s2 < 2; ++s2)
            mma16816h(acc[mi][nj2*2+s2], ah4[mi], bf[nj2][2*s2], bf[nj2][2*s2+1]);
    }
  }

  const float Dh = Dv[h];
  #pragma unroll
  for (int mi = 0; mi < 2; ++mi) {
    int row = wm + mi*16 + (lane >> 2);
    #pragma unroll
    for (int nj = 0; nj < 4; ++nj) {
      int col = wn + nj*8 + (lane & 3)*2;
      float2 x0 = *(const float2*)&g_xbc[rowbase + (size_t)row * cCD + h * cHD + col];
      float2 x1 = *(const float2*)&g_xbc[rowbase + (size_t)(row+8) * cCD + h * cHD + col];
      size_t y0 = ((size_t)(b * cL + c * cCK + row)) * cDS + h * cHD + col;
      size_t y1 = ((size_t)(b * cL + c * cCK + row + 8)) * cDS + h * cHD + col;
      *(float2*)&g_y[y0] = make_float2(acc[mi][nj][0] + Dh * x0.x,
                                       acc[mi][nj][1] + Dh * x0.y);
      *(float2*)&g_y[y1] = make_float2(acc[mi][nj][2] + Dh * x1.x,
                                       acc[mi][nj][3] + Dh * x1.y);
    }
  }
}

// ============= K7: gate (silu(z)) + RMSNorm + fp16 cvt (fused) ============
__global__ void __launch_bounds__(256) k_gate_norm(const float* __restrict__ norm_w)
{
  const int row = blockIdx.x;
  const int tid = threadIdx.x;
  const size_t zb = (size_t)row * cDP;
  const size_t yb = (size_t)row * cDS;
  float v[16];
  float ss = 0.0f;
  #pragma unroll
  for (int q = 0; q < 16; ++q) {
    int i = tid + q * 256;
    float z = g_zx[zb + i];
    float y = g_y[yb + i];
    float t = y * z * fsig(z);
    v[q] = t;
    ss += t * t;
  }
  #pragma unroll
  for (int o = 16; o > 0; o >>= 1) ss += __shfl_xor_sync(0xffffffffu, ss, o);
  __shared__ float red[8];
  if ((tid & 31) == 0) red[tid >> 5] = ss;
  __syncthreads();
  float tot = 0.0f;
  #pragma unroll
  for (int j = 0; j < 8; ++j) tot += red[j];
  const float scale = rsqrtf(tot / (float)cDS + cEPS);
  #pragma unroll
  for (int q = 0; q < 16; ++q) {
    int i = tid + q * 256;
    float t = v[q] * scale * norm_w[i];
    __half hh = __float2half_rn(t);
    g_ah[yb + i] = *(unsigned short*)&hh;
  }
}

// ============= K9: out + reverse(out) =====================================
__global__ void __launch_bounds__(256) k_revadd(float* __restrict__ out)
{
  const int idx4 = blockIdx.x * 256 + threadIdx.x;
  const int tot4 = cB * cL * cDM / 4;
  if (idx4 >= tot4) return;
  const int i = idx4 * 4;
  const int b = i / (cL * cDM);
  const int r = i - b * (cL * cDM);
  const int l = r / cDM;
  const int d = r - l * cDM;
  const size_t rev = ((size_t)b * cL + (cL - 1 - l)) * cDM + d;
  float4 a = *(const float4*)(&g_o[i]);
  float4 c = *(const float4*)(&g_o[rev]);
  a.x += c.x; a.y += c.y; a.z += c.z; a.w += c.w;
  *(float4*)(out + i) = a;
}

// ==========================================================================
extern "C" void kernel_launch(void* const* d_in, const int* in_sizes, int n_in,
                              void* d_out, int out_size) {
  const float* u       = (const float*)d_in[0];
  const float* W_in    = (const float*)d_in[1];
  const float* conv_w  = (const float*)d_in[2];
  const float* conv_b  = (const float*)d_in[3];
  const float* dt_bias = (const float*)d_in[4];
  const float* A_log   = (const float*)d_in[5];
  const float* Dv      = (const float*)d_in[6];
  const float* norm_w  = (const float*)d_in[7];
  const float* W_out   = (const float*)d_in[8];
  float* out = (float*)d_out;

  float* zx; cudaGetSymbolAddress((void**)&zx, g_zx);
  float* ob; cudaGetSymbolAddress((void**)&ob, g_o);
  unsigned short *ah, *bh, *b2h;
  cudaGetSymbolAddress((void**)&ah,  g_ah);
  cudaGetSymbolAddress((void**)&bh,  g_bh);
  cudaGetSymbolAddress((void**)&b2h, g_b2h);

  cudaFuncSetAttribute(gemm_mma, cudaFuncAttributeMaxDynamicSharedMemorySize,
                       SMEM_GEMM);
  cudaFuncSetAttribute(k_gmat, cudaFuncAttributeMaxDynamicSharedMemorySize,
                       G_SMEM);
  cudaFuncSetAttribute(k_states, cudaFuncAttributeMaxDynamicSharedMemorySize,
                       S_SMEM);
  cudaFuncSetAttribute(k_ssd_y, cudaFuncAttributeMaxDynamicSharedMemorySize,
                       Y_SMEM);

  const int M = cB * cL;   // 4096

  // --- fused prep: u, W_in (padded), W_out -> fp16 (single launch) ---
  k_cvt_all<<<(unsigned)((CV_TOT + 255) / 256), 256>>>(
      u, W_in, W_out, ah, bh, b2h);
  // --- GEMM1: zx[4096, 8512] ---
  {
    dim3 grid(cNPAD1 / 128, M / 128);
    gemm_mma<<<grid, 256, SMEM_GEMM>>>(
        (const __half*)ah, (const __half*)bh, zx, M, cDP, cDM);
  }
  // --- conv + silu + dt ---
  k_conv<<<cB * cL / CTL, 256>>>(conv_w, conv_b, dt_bias);
  // --- chunk states (fp16 mma, fused scan) ---
  { dim3 grid(cNH, cNC, cB); k_states<<<grid, 256, S_SMEM>>>(A_log); }
  // --- carry scan (4-way split) ---
  k_carry<<<cB * cNH * 4, 256>>>();
  // --- G (fp16 mma) ---
  { dim3 grid(cNC, cB); k_gmat<<<grid, 256, G_SMEM>>>(); }
  // --- Y (fp16 mma, single-stage) ---
  { dim3 grid(cNH, cNC, cB); k_ssd_y<<<grid, 256, Y_SMEM>>>(Dv); }
  // --- gate + rmsnorm + fp16 cvt (fused) ---
  k_gate_norm<<<cB * cL, 256>>>(norm_w);
  // --- GEMM2: o[4096, 2048] ---
  {
    dim3 grid(cDM / 128, M / 128);
    gemm_mma<<<grid, 256, SMEM_GEMM>>>(
        (const __half*)ah, (const __half*)b2h, ob, M, cDM, cDS);
  }
  // --- out + reverse(out) ---
  k_revadd<<<(cB * cL * cDM / 4 + 255) / 256, 256>>>(out);
}